// round 8
// baseline (speedup 1.0000x reference)
#include <cuda_runtime.h>
#include <cuda_bf16.h>
#include <cuda_fp16.h>
#include <math.h>
#include <stdint.h>

#define IN_DIM 256
#define OUT_DIM 256
#define DK 32
#define MAXN 50000
#define MAXE 800000

// ---------------- static device scratch (no cudaMalloc anywhere) ------------
__device__ __nv_bfloat16 g_AGh[MAXN * OUT_DIM];
__device__ __nv_bfloat16 g_AGl[MAXN * OUT_DIM];
__device__ __nv_bfloat16 g_Wh [4 * OUT_DIM * IN_DIM];
__device__ __nv_bfloat16 g_Wl [4 * OUT_DIM * IN_DIM];
__device__ __half g_Qh [MAXN * OUT_DIM];
__device__ __half g_Krh[MAXN * OUT_DIM];
__device__ __half g_Vh [MAXN * OUT_DIM];
__device__ int   g_deg[MAXN];
__device__ int   g_ptr[MAXN + 1];
__device__ int   g_cur[MAXN];
__device__ int   g_src[MAXE];
__device__ int   g_bsum[128];

// ---------------- asm helpers (family-common: sm_80+) -------------------------
__device__ __forceinline__ uint32_t smem_u32(const void* p) {
    uint32_t a;
    asm("{ .reg .u64 t; cvta.to.shared.u64 t, %1; cvt.u32.u64 %0, t; }"
        : "=r"(a) : "l"(p));
    return a;
}
__device__ __forceinline__ void cp16(uint32_t dst, const void* src, uint32_t bytes) {
    asm volatile("cp.async.cg.shared.global [%0], [%1], 16, %2;"
                 :: "r"(dst), "l"(src), "r"(bytes));
}
#define CP_COMMIT() asm volatile("cp.async.commit_group;" ::: "memory")
#define CP_WAIT(n)  asm volatile("cp.async.wait_group %0;" :: "n"(n) : "memory")

__device__ __forceinline__ void ldm_x4(uint32_t* r, uint32_t addr) {
    asm volatile("ldmatrix.sync.aligned.m8n8.x4.shared.b16 {%0,%1,%2,%3}, [%4];"
                 : "=r"(r[0]), "=r"(r[1]), "=r"(r[2]), "=r"(r[3]) : "r"(addr));
}
__device__ __forceinline__ void ldm_x2(uint32_t* r, uint32_t addr) {
    asm volatile("ldmatrix.sync.aligned.m8n8.x2.shared.b16 {%0,%1}, [%2];"
                 : "=r"(r[0]), "=r"(r[1]) : "r"(addr));
}
__device__ __forceinline__ void mma_bf16(float* c, const uint32_t* a, const uint32_t* b) {
    asm volatile("mma.sync.aligned.m16n8k16.row.col.f32.bf16.bf16.f32 "
                 "{%0,%1,%2,%3}, {%4,%5,%6,%7}, {%8,%9}, {%0,%1,%2,%3};"
                 : "+f"(c[0]), "+f"(c[1]), "+f"(c[2]), "+f"(c[3])
                 : "r"(a[0]), "r"(a[1]), "r"(a[2]), "r"(a[3]), "r"(b[0]), "r"(b[1]));
}

// ---------------- split helpers -----------------------------------------------
__device__ __forceinline__ void split2(float x, float y,
                                       __nv_bfloat162& hi, __nv_bfloat162& lo) {
    __nv_bfloat16 hx = __float2bfloat16(x), hy = __float2bfloat16(y);
    __nv_bfloat16 lx = __float2bfloat16(x - __bfloat162float(hx));
    __nv_bfloat16 ly = __float2bfloat16(y - __bfloat162float(hy));
    hi = __nv_bfloat162(hx, hy);
    lo = __nv_bfloat162(lx, ly);
}
// all 4 weight matrices in one launch
__global__ void cvt_split_w4_kernel(const float4* __restrict__ W0,
                                    const float4* __restrict__ W1,
                                    const float4* __restrict__ W2,
                                    const float4* __restrict__ W3) {
    __nv_bfloat162* hi = reinterpret_cast<__nv_bfloat162*>(g_Wh);
    __nv_bfloat162* lo = reinterpret_cast<__nv_bfloat162*>(g_Wl);
    const float4* Ws[4] = {W0, W1, W2, W3};
    for (int i = blockIdx.x * blockDim.x + threadIdx.x; i < 65536;
         i += gridDim.x * blockDim.x) {
        float4 v = Ws[i >> 14][i & 16383];
        split2(v.x, v.y, hi[2 * i],     lo[2 * i]);
        split2(v.z, v.w, hi[2 * i + 1], lo[2 * i + 1]);
    }
}

// ---------------- CSR build ----------------------------------------------------
__global__ void count_kernel(const int* __restrict__ col, int E) {
    for (int e = blockIdx.x * blockDim.x + threadIdx.x; e < E;
         e += gridDim.x * blockDim.x)
        atomicAdd(&g_deg[col[e]], 1);
}
__global__ void scan_partial_kernel(int n) {
    __shared__ int sh[1024];
    int i = blockIdx.x * 1024 + threadIdx.x;
    int v = (i < n) ? g_deg[i] : 0;
    sh[threadIdx.x] = v;
    __syncthreads();
    for (int off = 1; off < 1024; off <<= 1) {
        int t = (threadIdx.x >= off) ? sh[threadIdx.x - off] : 0;
        __syncthreads();
        sh[threadIdx.x] += t;
        __syncthreads();
    }
    if (i < n) g_ptr[i] = sh[threadIdx.x] - v;
    if (threadIdx.x == 1023) g_bsum[blockIdx.x] = sh[1023];
}
__global__ void scan_bsums_kernel(int nb) {
    if (threadIdx.x == 0) {
        int s = 0;
        for (int b = 0; b < nb; b++) { int t = g_bsum[b]; g_bsum[b] = s; s += t; }
    }
}
__global__ void scan_add_kernel(int n, int E) {
    int i = blockIdx.x * blockDim.x + threadIdx.x;
    if (i < n) {
        int p = g_ptr[i] + g_bsum[i >> 10];
        g_ptr[i] = p;
        g_cur[i] = p;
    }
    if (i == 0) g_ptr[n] = E;
}
__global__ void scatter_kernel(const int* __restrict__ row,
                               const int* __restrict__ col, int E) {
    for (int e = blockIdx.x * blockDim.x + threadIdx.x; e < E;
         e += gridDim.x * blockDim.x) {
        int pos = atomicAdd(&g_cur[col[e]], 1);
        g_src[pos] = row[e];
    }
}

// ---------------- fused-convert 3M-split HMMA GEMM ----------------------------
// C[M,256] = A[M,256] @ W^T + bias(+bias2).  CTA tile 128x256 (full N), 512 thr.
// K=256 as 4 physical k-tiles of 64; each tile runs 3 passes:
//   Ah*Wh + Ah*Wl + Al*Wh  (same accumulator).
// A source: either fp32 (user/item concat, split on the fly) or bf16 pre-split.
// smem per stage 96KB: Ah(16K) Al(16K) Wh(32K) Wl(32K); 2 stages.
#define S_AH 0
#define S_AL 16384
#define S_WH 32768
#define S_WL 65536
#define STG  98304
#define GEMM_SMEM (2 * STG)

__global__ void __launch_bounds__(512, 1)
gemm_fused_kernel(const float* __restrict__ Au, const float* __restrict__ Ai, int NU,
                  const __nv_bfloat16* __restrict__ Ahp, const __nv_bfloat16* __restrict__ Alp,
                  const __nv_bfloat16* __restrict__ Wh, const __nv_bfloat16* __restrict__ Wl,
                  const float* __restrict__ bias, const float* __restrict__ bias2,
                  float* __restrict__ C, __half* __restrict__ Ch, int M) {
    extern __shared__ char smem[];
    const uint32_t sb = smem_u32(smem);
    const int tid = threadIdx.x, wid = tid >> 5, lid = tid & 31;
    const int bm = blockIdx.x * 128;
    const int wr = wid & 3;       // warp row: 4 x 32
    const int wc = wid >> 2;      // warp col: 4 x 64
    const bool f32path = (Au != nullptr);

    float acc[2][8][4];
#pragma unroll
    for (int i = 0; i < 2; i++)
#pragma unroll
        for (int j = 0; j < 8; j++)
#pragma unroll
            for (int k = 0; k < 4; k++) acc[i][j][k] = 0.f;

    // ---- loaders ----
    auto cpW = [&](int kt, uint32_t stg) {
#pragma unroll
        for (int j = 0; j < 4; j++) {
            int idx = tid + j * 512;
            int r = idx >> 3, c = idx & 7;
            uint32_t sw = (uint32_t)r * 128 + (((uint32_t)(c ^ (r & 7))) << 4);
            cp16(sb + stg + S_WH + sw,
                 (const char*)Wh + (size_t)r * 512 + kt * 128 + c * 16, 16u);
            cp16(sb + stg + S_WL + sw,
                 (const char*)Wl + (size_t)r * 512 + kt * 128 + c * 16, 16u);
        }
    };
    auto cpA_bf16 = [&](int kt, uint32_t stg) {
#pragma unroll
        for (int j = 0; j < 2; j++) {
            int idx = tid + j * 512;
            int r = idx >> 3, c = idx & 7;
            int grow = bm + r;
            uint32_t bytes = (grow < M) ? 16u : 0u;
            uint32_t sw = (uint32_t)r * 128 + (((uint32_t)(c ^ (r & 7))) << 4);
            cp16(sb + stg + S_AH + sw,
                 (const char*)Ahp + (size_t)grow * 512 + kt * 128 + c * 16, bytes);
            cp16(sb + stg + S_AL + sw,
                 (const char*)Alp + (size_t)grow * 512 + kt * 128 + c * 16, bytes);
        }
    };
    float4 av[4];
    auto ldA_f32 = [&](int kt) {
#pragma unroll
        for (int j = 0; j < 4; j++) {
            int idx = tid + j * 512;
            int r = idx >> 4, c4 = idx & 15;
            int grow = bm + r;
            if (grow < M) {
                const float* src = (grow < NU) ? (Au + (size_t)grow * 256)
                                               : (Ai + (size_t)(grow - NU) * 256);
                av[j] = *(const float4*)(src + kt * 64 + c4 * 4);
            } else {
                av[j] = make_float4(0.f, 0.f, 0.f, 0.f);
            }
        }
    };
    auto stA_f32 = [&](uint32_t stg) {
#pragma unroll
        for (int j = 0; j < 4; j++) {
            int idx = tid + j * 512;
            int r = idx >> 4, c4 = idx & 15;
            __nv_bfloat162 h0, l0, h1, l1;
            split2(av[j].x, av[j].y, h0, l0);
            split2(av[j].z, av[j].w, h1, l1);
            int ch = c4 >> 1, half8 = (c4 & 1) * 8;
            uint32_t sw = (uint32_t)r * 128 + (((uint32_t)(ch ^ (r & 7))) << 4) + half8;
            uint2 hv, lv;
            hv.x = *(uint32_t*)&h0; hv.y = *(uint32_t*)&h1;
            lv.x = *(uint32_t*)&l0; lv.y = *(uint32_t*)&l1;
            *(uint2*)(smem + stg + S_AH + sw) = hv;
            *(uint2*)(smem + stg + S_AL + sw) = lv;
        }
    };
    auto compute = [&](uint32_t stg) {
#pragma unroll
        for (int p = 0; p < 3; p++) {
            const uint32_t aoff = sb + stg + ((p == 2) ? S_AL : S_AH);
            const uint32_t woff = sb + stg + ((p == 1) ? S_WL : S_WH);
#pragma unroll
            for (int ks = 0; ks < 4; ks++) {
                uint32_t a[2][4], b[8][2];
#pragma unroll
                for (int ma = 0; ma < 2; ma++) {
                    int ar = wr * 32 + ma * 16 + (lid & 15);
                    int ch = ks * 2 + (lid >> 4);
                    ldm_x4(a[ma], aoff + ar * 128 + ((ch ^ (ar & 7)) << 4));
                }
#pragma unroll
                for (int na = 0; na < 8; na++) {
                    int nr = wc * 64 + na * 8 + (lid & 7);
                    int ch = ks * 2 + ((lid >> 3) & 1);
                    ldm_x2(b[na], woff + nr * 128 + ((ch ^ (nr & 7)) << 4));
                }
#pragma unroll
                for (int ma = 0; ma < 2; ma++)
#pragma unroll
                    for (int na = 0; na < 8; na++)
                        mma_bf16(acc[ma][na], a[ma], b[na]);
            }
        }
    };

    // ---- prologue: tile 0 -> stage 0 ----
    if (f32path) { ldA_f32(0); stA_f32(0); }
    else cpA_bf16(0, 0);
    cpW(0, 0);
    CP_COMMIT(); CP_WAIT(0);
    __syncthreads();

    // ---- main loop ----
#pragma unroll
    for (int kt = 0; kt < 4; kt++) {
        const uint32_t st  = (kt & 1) * STG;
        const uint32_t nst = ((kt + 1) & 1) * STG;
        const bool pf = (kt < 3);
        if (pf) {
            if (f32path) ldA_f32(kt + 1);     // LDG issued, latency hidden by MMA
            else cpA_bf16(kt + 1, nst);
            cpW(kt + 1, nst);
            CP_COMMIT();
        }
        compute(st);
        if (pf) {
            if (f32path) stA_f32(nst);
            CP_WAIT(0);
        }
        __syncthreads();
    }

    // ---- epilogue ----
    const int g = lid >> 2;
    const int tg = (lid & 3) * 2;
#pragma unroll
    for (int ma = 0; ma < 2; ma++) {
        int mr = bm + wr * 32 + ma * 16 + g;
#pragma unroll
        for (int na = 0; na < 8; na++) {
            int nc = wc * 64 + na * 8 + tg;
            float b0 = bias[nc], b1 = bias[nc + 1];
            if (bias2) { b0 += bias2[nc]; b1 += bias2[nc + 1]; }
            float o00 = acc[ma][na][0] + b0, o01 = acc[ma][na][1] + b1;
            float o10 = acc[ma][na][2] + b0, o11 = acc[ma][na][3] + b1;
            if (Ch) {
                if (mr < M)
                    *(__half2*)(Ch + (size_t)mr * OUT_DIM + nc) = __floats2half2_rn(o00, o01);
                if (mr + 8 < M)
                    *(__half2*)(Ch + (size_t)(mr + 8) * OUT_DIM + nc) = __floats2half2_rn(o10, o11);
            } else {
                if (mr < M)
                    *(float2*)(C + (size_t)mr * OUT_DIM + nc) = make_float2(o00, o01);
                if (mr + 8 < M)
                    *(float2*)(C + (size_t)(mr + 8) * OUT_DIM + nc) = make_float2(o10, o11);
            }
        }
    }
}

// ---------------- per-node attention, fp16 gathers, bf16-split output ---------
__global__ void __launch_bounds__(128)
attn_kernel(int N) {
    const int n = blockIdx.x;
    if (n >= N) return;
    const int tid = threadIdx.x;
    const int w = tid >> 5, lid = tid & 31;
    const int head = w * 2 + (lid >> 4);
    const int sl = lid & 15;
    const int h2off = head * 16 + sl;
    const int beg = g_ptr[n];
    const int end = g_ptr[n + 1];

    const __half2* Qh2  = reinterpret_cast<const __half2*>(g_Qh);
    const __half2* Krh2 = reinterpret_cast<const __half2*>(g_Krh);
    const __half2* Vh2  = reinterpret_cast<const __half2*>(g_Vh);

    const float2 qf = __half22float2(Qh2[(size_t)n * 128 + h2off]);
    const float inv_sqrt_dk = 0.17677669529663689f;

    float m = -INFINITY, s = 0.f;
    float ax = 0.f, ay = 0.f;

    for (int i = beg; i < end; i++) {
        int r = g_src[i];
        float2 kf = __half22float2(Krh2[(size_t)r * 128 + h2off]);
        float2 vf = __half22float2(Vh2[(size_t)r * 128 + h2off]);
        float p = qf.x * kf.x + qf.y * kf.y;
        p += __shfl_xor_sync(0xffffffffu, p, 8);
        p += __shfl_xor_sync(0xffffffffu, p, 4);
        p += __shfl_xor_sync(0xffffffffu, p, 2);
        p += __shfl_xor_sync(0xffffffffu, p, 1);
        float xsc = p * inv_sqrt_dk;
        float nm = fmaxf(m, xsc);
        float scale = __expf(m - nm);
        float ex = __expf(xsc - nm);
        s = s * scale + ex;
        ax = ax * scale + ex * vf.x;
        ay = ay * scale + ex * vf.y;
        m = nm;
    }

    float ox = 0.f, oy = 0.f;
    if (s > 0.f) { float inv = 1.f / s; ox = ax * inv; oy = ay * inv; }
    __nv_bfloat162 hi, lo;
    split2(ox, oy, hi, lo);
    reinterpret_cast<__nv_bfloat162*>(g_AGh)[(size_t)n * 128 + h2off] = hi;
    reinterpret_cast<__nv_bfloat162*>(g_AGl)[(size_t)n * 128 + h2off] = lo;
}

// ---------------- launch --------------------------------------------------------
extern "C" void kernel_launch(void* const* d_in, const int* in_sizes, int n_in,
                              void* d_out, int out_size) {
    const float* x    = (const float*)d_in[0];
    const int*   row  = (const int*)  d_in[1];
    const int*   col  = (const int*)  d_in[2];
    const float* rel  = (const float*)d_in[3];
    const float* user = (const float*)d_in[4];
    const float* item = (const float*)d_in[5];
    const float* Wq   = (const float*)d_in[6];
    const float* bq   = (const float*)d_in[7];
    const float* Wk   = (const float*)d_in[8];
    const float* bk   = (const float*)d_in[9];
    const float* Wv   = (const float*)d_in[10];
    const float* bv   = (const float*)d_in[11];
    const float* Wo   = (const float*)d_in[12];
    const float* bo   = (const float*)d_in[13];
    float* out = (float*)d_out;

    const int N  = in_sizes[0] / IN_DIM;
    const int E  = in_sizes[1];
    const int NU = in_sizes[4] / IN_DIM;

    __half *dQh, *dKrh, *dVh;
    __nv_bfloat16 *dAGh, *dAGl, *dWh, *dWl;
    int* dDeg;
    cudaGetSymbolAddress((void**)&dQh,  g_Qh);
    cudaGetSymbolAddress((void**)&dKrh, g_Krh);
    cudaGetSymbolAddress((void**)&dVh,  g_Vh);
    cudaGetSymbolAddress((void**)&dAGh, g_AGh);
    cudaGetSymbolAddress((void**)&dAGl, g_AGl);
    cudaGetSymbolAddress((void**)&dWh,  g_Wh);
    cudaGetSymbolAddress((void**)&dWl,  g_Wl);
    cudaGetSymbolAddress((void**)&dDeg, g_deg);

    cudaFuncSetAttribute(gemm_fused_kernel,
                         cudaFuncAttributeMaxDynamicSharedMemorySize, GEMM_SMEM);

    // 1. split weights (one launch)
    cvt_split_w4_kernel<<<256, 256>>>((const float4*)Wq, (const float4*)Wk,
                                      (const float4*)Wv, (const float4*)Wo);

    // 2. CSR build by destination (col)
    cudaMemsetAsync(dDeg, 0, (size_t)N * sizeof(int), 0);
    count_kernel<<<(E + 255) / 256, 256>>>(col, E);
    int nb = (N + 1023) / 1024;
    scan_partial_kernel<<<nb, 1024>>>(N);
    scan_bsums_kernel<<<1, 32>>>(nb);
    scan_add_kernel<<<(N + 255) / 256, 256>>>(N, E);
    scatter_kernel<<<(E + 255) / 256, 256>>>(row, col, E);

    // 3. projections (fused fp32->split-bf16 GEMM) -> fp16 intermediates
    int gx = (N + 127) / 128;
    gemm_fused_kernel<<<gx, 512, GEMM_SMEM>>>(user, item, NU, nullptr, nullptr,
                                              dWh + 0 * 65536, dWl + 0 * 65536,
                                              bq, nullptr, nullptr, dQh, N);
    gemm_fused_kernel<<<gx, 512, GEMM_SMEM>>>(user, item, NU, nullptr, nullptr,
                                              dWh + 1 * 65536, dWl + 1 * 65536,
                                              bk, rel, nullptr, dKrh, N);
    gemm_fused_kernel<<<gx, 512, GEMM_SMEM>>>(x, x, N, nullptr, nullptr,
                                              dWh + 2 * 65536, dWl + 2 * 65536,
                                              bv, nullptr, nullptr, dVh, N);

    // 4. attention (fp16 gathers, writes bf16 hi/lo split directly)
    attn_kernel<<<N, 128>>>(N);

    // 5. output projection (bf16 pre-split A) -> fp32 out
    gemm_fused_kernel<<<gx, 512, GEMM_SMEM>>>(nullptr, nullptr, 0, dAGh, dAGl,
                                              dWh + 3 * 65536, dWl + 3 * 65536,
                                              bo, nullptr, out, nullptr, N);
}

// round 9
// speedup vs baseline: 1.3227x; 1.3227x over previous
#include <cuda_runtime.h>
#include <cuda_bf16.h>
#include <cuda_fp16.h>
#include <math.h>
#include <stdint.h>

#define IN_DIM 256
#define OUT_DIM 256
#define DK 32
#define MAXN 50000
#define MAXE 800000

// ---------------- static device scratch (no cudaMalloc anywhere) ------------
__device__ __nv_bfloat16 g_TEh[MAXN * IN_DIM];
__device__ __nv_bfloat16 g_TEl[MAXN * IN_DIM];
__device__ __nv_bfloat16 g_Xh [MAXN * IN_DIM];
__device__ __nv_bfloat16 g_Xl [MAXN * IN_DIM];
__device__ __nv_bfloat16 g_AGh[MAXN * OUT_DIM];
__device__ __nv_bfloat16 g_AGl[MAXN * OUT_DIM];
__device__ __nv_bfloat16 g_Wh [4 * OUT_DIM * IN_DIM];
__device__ __nv_bfloat16 g_Wl [4 * OUT_DIM * IN_DIM];
__device__ __half g_Qh [MAXN * OUT_DIM];
__device__ __half g_KVh[MAXN * 2 * OUT_DIM];   // interleaved: [n][2d]=K, [n][2d+1]=V
__device__ int   g_deg[MAXN];
__device__ int   g_ptr[MAXN + 1];
__device__ int   g_cur[MAXN];
__device__ int   g_src[MAXE];
__device__ int   g_bsum[128];

// ---------------- asm helpers (family-common: sm_80+) -------------------------
__device__ __forceinline__ uint32_t smem_u32(const void* p) {
    uint32_t a;
    asm("{ .reg .u64 t; cvta.to.shared.u64 t, %1; cvt.u32.u64 %0, t; }"
        : "=r"(a) : "l"(p));
    return a;
}
__device__ __forceinline__ void cp16(uint32_t dst, const void* src, uint32_t bytes) {
    asm volatile("cp.async.cg.shared.global [%0], [%1], 16, %2;"
                 :: "r"(dst), "l"(src), "r"(bytes));
}
#define CP_COMMIT() asm volatile("cp.async.commit_group;" ::: "memory")
#define CP_WAIT(n)  asm volatile("cp.async.wait_group %0;" :: "n"(n) : "memory")

__device__ __forceinline__ void ldm_x4(uint32_t* r, uint32_t addr) {
    asm volatile("ldmatrix.sync.aligned.m8n8.x4.shared.b16 {%0,%1,%2,%3}, [%4];"
                 : "=r"(r[0]), "=r"(r[1]), "=r"(r[2]), "=r"(r[3]) : "r"(addr));
}
__device__ __forceinline__ void ldm_x2(uint32_t* r, uint32_t addr) {
    asm volatile("ldmatrix.sync.aligned.m8n8.x2.shared.b16 {%0,%1}, [%2];"
                 : "=r"(r[0]), "=r"(r[1]) : "r"(addr));
}
__device__ __forceinline__ void mma_bf16(float* c, const uint32_t* a, const uint32_t* b) {
    asm volatile("mma.sync.aligned.m16n8k16.row.col.f32.bf16.bf16.f32 "
                 "{%0,%1,%2,%3}, {%4,%5,%6,%7}, {%8,%9}, {%0,%1,%2,%3};"
                 : "+f"(c[0]), "+f"(c[1]), "+f"(c[2]), "+f"(c[3])
                 : "r"(a[0]), "r"(a[1]), "r"(a[2]), "r"(a[3]), "r"(b[0]), "r"(b[1]));
}

// ---------------- split-bf16 conversion kernels -------------------------------
__device__ __forceinline__ void split2(float x, float y,
                                       __nv_bfloat162& hi, __nv_bfloat162& lo) {
    __nv_bfloat16 hx = __float2bfloat16(x), hy = __float2bfloat16(y);
    __nv_bfloat16 lx = __float2bfloat16(x - __bfloat162float(hx));
    __nv_bfloat16 ly = __float2bfloat16(y - __bfloat162float(hy));
    hi = __nv_bfloat162(hx, hy);
    lo = __nv_bfloat162(lx, ly);
}
__global__ void cvt_split_kernel(const float4* __restrict__ src,
                                 __nv_bfloat162* __restrict__ hi,
                                 __nv_bfloat162* __restrict__ lo, int n4) {
    for (int i = blockIdx.x * blockDim.x + threadIdx.x; i < n4;
         i += gridDim.x * blockDim.x) {
        float4 v = src[i];
        split2(v.x, v.y, hi[2 * i],     lo[2 * i]);
        split2(v.z, v.w, hi[2 * i + 1], lo[2 * i + 1]);
    }
}
__global__ void cvt_split_te_kernel(const float4* __restrict__ user,
                                    const float4* __restrict__ item,
                                    int nu4, int total4) {
    __nv_bfloat162* hi = reinterpret_cast<__nv_bfloat162*>(g_TEh);
    __nv_bfloat162* lo = reinterpret_cast<__nv_bfloat162*>(g_TEl);
    for (int i = blockIdx.x * blockDim.x + threadIdx.x; i < total4;
         i += gridDim.x * blockDim.x) {
        float4 v = (i < nu4) ? user[i] : item[i - nu4];
        split2(v.x, v.y, hi[2 * i],     lo[2 * i]);
        split2(v.z, v.w, hi[2 * i + 1], lo[2 * i + 1]);
    }
}
__global__ void cvt_split_w4_kernel(const float4* __restrict__ W0,
                                    const float4* __restrict__ W1,
                                    const float4* __restrict__ W2,
                                    const float4* __restrict__ W3) {
    __nv_bfloat162* hi = reinterpret_cast<__nv_bfloat162*>(g_Wh);
    __nv_bfloat162* lo = reinterpret_cast<__nv_bfloat162*>(g_Wl);
    const float4* Ws[4] = {W0, W1, W2, W3};
    for (int i = blockIdx.x * blockDim.x + threadIdx.x; i < 65536;
         i += gridDim.x * blockDim.x) {
        float4 v = Ws[i >> 14][i & 16383];
        split2(v.x, v.y, hi[2 * i],     lo[2 * i]);
        split2(v.z, v.w, hi[2 * i + 1], lo[2 * i + 1]);
    }
}

// ---------------- CSR build ----------------------------------------------------
__global__ void count_kernel(const int* __restrict__ col, int E) {
    for (int e = blockIdx.x * blockDim.x + threadIdx.x; e < E;
         e += gridDim.x * blockDim.x)
        atomicAdd(&g_deg[col[e]], 1);
}
__global__ void scan_partial_kernel(int n) {
    __shared__ int sh[1024];
    int i = blockIdx.x * 1024 + threadIdx.x;
    int v = (i < n) ? g_deg[i] : 0;
    sh[threadIdx.x] = v;
    __syncthreads();
    for (int off = 1; off < 1024; off <<= 1) {
        int t = (threadIdx.x >= off) ? sh[threadIdx.x - off] : 0;
        __syncthreads();
        sh[threadIdx.x] += t;
        __syncthreads();
    }
    if (i < n) g_ptr[i] = sh[threadIdx.x] - v;
    if (threadIdx.x == 1023) g_bsum[blockIdx.x] = sh[1023];
}
__global__ void scan_bsums_kernel(int nb) {
    if (threadIdx.x == 0) {
        int s = 0;
        for (int b = 0; b < nb; b++) { int t = g_bsum[b]; g_bsum[b] = s; s += t; }
    }
}
__global__ void scan_add_kernel(int n, int E) {
    int i = blockIdx.x * blockDim.x + threadIdx.x;
    if (i < n) {
        int p = g_ptr[i] + g_bsum[i >> 10];
        g_ptr[i] = p;
        g_cur[i] = p;
    }
    if (i == 0) g_ptr[n] = E;
}
__global__ void scatter_kernel(const int* __restrict__ row,
                               const int* __restrict__ col, int E) {
    for (int e = blockIdx.x * blockDim.x + threadIdx.x; e < E;
         e += gridDim.x * blockDim.x) {
        int pos = atomicAdd(&g_cur[col[e]], 1);
        g_src[pos] = row[e];
    }
}

// ---------------- 3M-split bf16 HMMA GEMM (R6 shape: 128x128, 256 thr) --------
// Output modes: fp32 C; fp16 Ch with element stride cs (1 = dense, 2 = interleave)
// and phase cp (0 = K slots, 1 = V slots).
#define NKT 12
#define GEMM_SMEM (4 * 16384)

__global__ void __launch_bounds__(256, 2)
gemm3m_kernel(const __nv_bfloat16* __restrict__ Ah, const __nv_bfloat16* __restrict__ Al,
              const __nv_bfloat16* __restrict__ Wh, const __nv_bfloat16* __restrict__ Wl,
              const float* __restrict__ bias, const float* __restrict__ bias2,
              float* __restrict__ C, __half* __restrict__ Ch, int cs, int cp, int M) {
    extern __shared__ char smem[];
    const uint32_t sb = smem_u32(smem);
    const int tid = threadIdx.x, wid = tid >> 5, lid = tid & 31;
    const int bm = blockIdx.x * 128;
    const int bn = blockIdx.y * 128;
    const int wm = (wid >> 2) * 64;
    const int wn = (wid & 3) * 32;

    float acc[4][4][4];
#pragma unroll
    for (int i = 0; i < 4; i++)
#pragma unroll
        for (int j = 0; j < 4; j++)
#pragma unroll
            for (int k = 0; k < 4; k++) acc[i][j][k] = 0.f;

    auto load_tile = [&](int kt, int stage) {
        const int seg = kt >> 2;
        const int koff = (kt & 3) * 64;
        const __nv_bfloat16* As = (seg == 2) ? Al : Ah;
        const __nv_bfloat16* Ws = (seg == 1) ? Wl : Wh;
        const uint32_t uA = sb + stage * 16384;
        const uint32_t uB = sb + 32768 + stage * 16384;
#pragma unroll
        for (int i = tid; i < 1024; i += 256) {
            int r = i >> 3, c = i & 7;
            int grow = bm + r;
            const char* g = (const char*)As + (size_t)grow * 512 + koff * 2 + c * 16;
            uint32_t d = uA + r * 128 + ((c ^ (r & 7)) << 4);
            cp16(d, g, (grow < M) ? 16u : 0u);
        }
#pragma unroll
        for (int i = tid; i < 1024; i += 256) {
            int r = i >> 3, c = i & 7;
            const char* g = (const char*)Ws + (size_t)(bn + r) * 512 + koff * 2 + c * 16;
            uint32_t d = uB + r * 128 + ((c ^ (r & 7)) << 4);
            cp16(d, g, 16u);
        }
        CP_COMMIT();
    };

    load_tile(0, 0);

    for (int kt = 0; kt < NKT; kt++) {
        const int st = kt & 1;
        if (kt + 1 < NKT) {
            load_tile(kt + 1, (kt + 1) & 1);
            CP_WAIT(1);
        } else {
            CP_WAIT(0);
        }
        __syncthreads();

        const uint32_t uA = sb + st * 16384;
        const uint32_t uB = sb + 32768 + st * 16384;
#pragma unroll
        for (int ks = 0; ks < 4; ks++) {
            uint32_t a[4][4], b[4][2];
#pragma unroll
            for (int ma = 0; ma < 4; ma++) {
                int ar = wm + ma * 16 + (lid & 15);
                int ch = ks * 2 + (lid >> 4);
                ldm_x4(a[ma], uA + ar * 128 + ((ch ^ (ar & 7)) << 4));
            }
#pragma unroll
            for (int na = 0; na < 4; na++) {
                int nr = wn + na * 8 + (lid & 7);
                int ch = ks * 2 + ((lid >> 3) & 1);
                ldm_x2(b[na], uB + nr * 128 + ((ch ^ (nr & 7)) << 4));
            }
#pragma unroll
            for (int ma = 0; ma < 4; ma++)
#pragma unroll
                for (int na = 0; na < 4; na++)
                    mma_bf16(acc[ma][na], a[ma], b[na]);
        }
        __syncthreads();
    }

    const int g = lid >> 2;
    const int tg = (lid & 3) * 2;
    const int cstride = OUT_DIM * cs;   // row stride in halves for Ch mode
#pragma unroll
    for (int ma = 0; ma < 4; ma++) {
        int mr = bm + wm + ma * 16 + g;
#pragma unroll
        for (int na = 0; na < 4; na++) {
            int nc = bn + wn + na * 8 + tg;
            float b0 = bias[nc], b1 = bias[nc + 1];
            if (bias2) { b0 += bias2[nc]; b1 += bias2[nc + 1]; }
            float o00 = acc[ma][na][0] + b0, o01 = acc[ma][na][1] + b1;
            float o10 = acc[ma][na][2] + b0, o11 = acc[ma][na][3] + b1;
            if (Ch) {
                if (cs == 1) {
                    if (mr < M)
                        *(__half2*)(Ch + (size_t)mr * OUT_DIM + nc) = __floats2half2_rn(o00, o01);
                    if (mr + 8 < M)
                        *(__half2*)(Ch + (size_t)(mr + 8) * OUT_DIM + nc) = __floats2half2_rn(o10, o11);
                } else {
                    if (mr < M) {
                        Ch[(size_t)mr * cstride + 2 * nc + cp]       = __float2half_rn(o00);
                        Ch[(size_t)mr * cstride + 2 * (nc + 1) + cp] = __float2half_rn(o01);
                    }
                    if (mr + 8 < M) {
                        Ch[(size_t)(mr + 8) * cstride + 2 * nc + cp]       = __float2half_rn(o10);
                        Ch[(size_t)(mr + 8) * cstride + 2 * (nc + 1) + cp] = __float2half_rn(o11);
                    }
                }
            } else {
                if (mr < M)
                    *(float2*)(C + (size_t)mr * OUT_DIM + nc) = make_float2(o00, o01);
                if (mr + 8 < M)
                    *(float2*)(C + (size_t)(mr + 8) * OUT_DIM + nc) = make_float2(o10, o11);
            }
        }
    }
}

// ---------------- per-node attention: interleaved-KV gather, 2-edge ILP -------
// block = node (128 thr). warp w covers heads 2w,2w+1; 16-lane groups; 2 dims/lane.
// Scores are O(1) in magnitude -> direct exp (softmax ratio unchanged).
__global__ void __launch_bounds__(128)
attn_kernel(int N) {
    const int n = blockIdx.x;
    if (n >= N) return;
    const int tid = threadIdx.x;
    const int w = tid >> 5, lid = tid & 31;
    const int head = w * 2 + (lid >> 4);
    const int sl = lid & 15;
    const int h2off = head * 16 + sl;        // index into 128-wide (pair) row

    const int beg = g_ptr[n];
    const int end = g_ptr[n + 1];

    const __half2* Qh2 = reinterpret_cast<const __half2*>(g_Qh);
    const uint2*   KV  = reinterpret_cast<const uint2*>(g_KVh);   // 128 uint2 / row

    const float2 qf = __half22float2(Qh2[(size_t)n * 128 + h2off]);
    const float inv_sqrt_dk = 0.17677669529663689f;

    float s = 0.f, ax = 0.f, ay = 0.f;

    int i = beg;
    for (; i + 1 < end; i += 2) {
        int r0 = g_src[i], r1 = g_src[i + 1];
        uint2 kv0 = KV[(size_t)r0 * 128 + h2off];
        uint2 kv1 = KV[(size_t)r1 * 128 + h2off];
        float2 a0 = __half22float2(*(__half2*)&kv0.x);   // (k0, v0)
        float2 b0 = __half22float2(*(__half2*)&kv0.y);   // (k1, v1)
        float2 a1 = __half22float2(*(__half2*)&kv1.x);
        float2 b1 = __half22float2(*(__half2*)&kv1.y);
        float p0 = qf.x * a0.x + qf.y * b0.x;
        float p1 = qf.x * a1.x + qf.y * b1.x;
        p0 += __shfl_xor_sync(0xffffffffu, p0, 8);
        p1 += __shfl_xor_sync(0xffffffffu, p1, 8);
        p0 += __shfl_xor_sync(0xffffffffu, p0, 4);
        p1 += __shfl_xor_sync(0xffffffffu, p1, 4);
        p0 += __shfl_xor_sync(0xffffffffu, p0, 2);
        p1 += __shfl_xor_sync(0xffffffffu, p1, 2);
        p0 += __shfl_xor_sync(0xffffffffu, p0, 1);
        p1 += __shfl_xor_sync(0xffffffffu, p1, 1);
        float e0 = __expf(p0 * inv_sqrt_dk);
        float e1 = __expf(p1 * inv_sqrt_dk);
        s += e0 + e1;
        ax += e0 * a0.y + e1 * a1.y;
        ay += e0 * b0.y + e1 * b1.y;
    }
    if (i < end) {
        int r0 = g_src[i];
        uint2 kv0 = KV[(size_t)r0 * 128 + h2off];
        float2 a0 = __half22float2(*(__half2*)&kv0.x);
        float2 b0 = __half22float2(*(__half2*)&kv0.y);
        float p0 = qf.x * a0.x + qf.y * b0.x;
        p0 += __shfl_xor_sync(0xffffffffu, p0, 8);
        p0 += __shfl_xor_sync(0xffffffffu, p0, 4);
        p0 += __shfl_xor_sync(0xffffffffu, p0, 2);
        p0 += __shfl_xor_sync(0xffffffffu, p0, 1);
        float e0 = __expf(p0 * inv_sqrt_dk);
        s += e0;
        ax += e0 * a0.y;
        ay += e0 * b0.y;
    }

    float ox = 0.f, oy = 0.f;
    if (s > 0.f) { float inv = 1.f / s; ox = ax * inv; oy = ay * inv; }
    __nv_bfloat162 hi, lo;
    split2(ox, oy, hi, lo);
    reinterpret_cast<__nv_bfloat162*>(g_AGh)[(size_t)n * 128 + h2off] = hi;
    reinterpret_cast<__nv_bfloat162*>(g_AGl)[(size_t)n * 128 + h2off] = lo;
}

// ---------------- launch --------------------------------------------------------
extern "C" void kernel_launch(void* const* d_in, const int* in_sizes, int n_in,
                              void* d_out, int out_size) {
    const float* x    = (const float*)d_in[0];
    const int*   row  = (const int*)  d_in[1];
    const int*   col  = (const int*)  d_in[2];
    const float* rel  = (const float*)d_in[3];
    const float* user = (const float*)d_in[4];
    const float* item = (const float*)d_in[5];
    const float* Wq   = (const float*)d_in[6];
    const float* bq   = (const float*)d_in[7];
    const float* Wk   = (const float*)d_in[8];
    const float* bk   = (const float*)d_in[9];
    const float* Wv   = (const float*)d_in[10];
    const float* bv   = (const float*)d_in[11];
    const float* Wo   = (const float*)d_in[12];
    const float* bo   = (const float*)d_in[13];
    float* out = (float*)d_out;

    const int N  = in_sizes[0] / IN_DIM;
    const int E  = in_sizes[1];
    const int NU = in_sizes[4] / IN_DIM;

    __half *dQh, *dKVh;
    __nv_bfloat16 *dTEh, *dTEl, *dXh, *dXl, *dAGh, *dAGl, *dWh, *dWl;
    int* dDeg;
    cudaGetSymbolAddress((void**)&dQh,  g_Qh);
    cudaGetSymbolAddress((void**)&dKVh, g_KVh);
    cudaGetSymbolAddress((void**)&dTEh, g_TEh);
    cudaGetSymbolAddress((void**)&dTEl, g_TEl);
    cudaGetSymbolAddress((void**)&dXh,  g_Xh);
    cudaGetSymbolAddress((void**)&dXl,  g_Xl);
    cudaGetSymbolAddress((void**)&dAGh, g_AGh);
    cudaGetSymbolAddress((void**)&dAGl, g_AGl);
    cudaGetSymbolAddress((void**)&dWh,  g_Wh);
    cudaGetSymbolAddress((void**)&dWl,  g_Wl);
    cudaGetSymbolAddress((void**)&dDeg, g_deg);

    cudaFuncSetAttribute(gemm3m_kernel,
                         cudaFuncAttributeMaxDynamicSharedMemorySize, GEMM_SMEM);

    // 1. split-bf16 conversions
    {
        int total4 = N * (IN_DIM / 4);
        int nu4 = NU * (IN_DIM / 4);
        cvt_split_te_kernel<<<1024, 256>>>((const float4*)user, (const float4*)item,
                                           nu4, total4);
        cvt_split_kernel<<<1024, 256>>>((const float4*)x,
                                        (__nv_bfloat162*)dXh, (__nv_bfloat162*)dXl,
                                        total4);
        cvt_split_w4_kernel<<<256, 256>>>((const float4*)Wq, (const float4*)Wk,
                                          (const float4*)Wv, (const float4*)Wo);
    }

    // 2. CSR build by destination (col)
    cudaMemsetAsync(dDeg, 0, (size_t)N * sizeof(int), 0);
    count_kernel<<<(E + 255) / 256, 256>>>(col, E);
    int nb = (N + 1023) / 1024;
    scan_partial_kernel<<<nb, 1024>>>(N);
    scan_bsums_kernel<<<1, 32>>>(nb);
    scan_add_kernel<<<(N + 255) / 256, 256>>>(N, E);
    scatter_kernel<<<(E + 255) / 256, 256>>>(row, col, E);

    // 3. projections -> fp16 (Q dense; Kr/V interleaved into g_KVh)
    dim3 gg((N + 127) / 128, 2);
    gemm3m_kernel<<<gg, 256, GEMM_SMEM>>>(dTEh, dTEl, dWh + 0 * 65536, dWl + 0 * 65536,
                                          bq, nullptr, nullptr, dQh, 1, 0, N);
    gemm3m_kernel<<<gg, 256, GEMM_SMEM>>>(dTEh, dTEl, dWh + 1 * 65536, dWl + 1 * 65536,
                                          bk, rel,     nullptr, dKVh, 2, 0, N);
    gemm3m_kernel<<<gg, 256, GEMM_SMEM>>>(dXh,  dXl,  dWh + 2 * 65536, dWl + 2 * 65536,
                                          bv, nullptr, nullptr, dKVh, 2, 1, N);

    // 4. attention (single 8B KV load per lane per edge)
    attn_kernel<<<N, 128>>>(N);

    // 5. output projection -> fp32 out
    gemm3m_kernel<<<gg, 256, GEMM_SMEM>>>(dAGh, dAGl, dWh + 3 * 65536, dWl + 3 * 65536,
                                          bo, nullptr, out, nullptr, 1, 0, N);
}

// round 10
// speedup vs baseline: 1.3330x; 1.0078x over previous
#include <cuda_runtime.h>
#include <cuda_bf16.h>
#include <cuda_fp16.h>
#include <math.h>
#include <stdint.h>

#define IN_DIM 256
#define OUT_DIM 256
#define DK 32
#define MAXN 50000
#define MAXE 800000

// ---------------- static device scratch (no cudaMalloc anywhere) ------------
__device__ __nv_bfloat16 g_TEh[MAXN * IN_DIM];
__device__ __nv_bfloat16 g_TEl[MAXN * IN_DIM];
__device__ __nv_bfloat16 g_Xh [MAXN * IN_DIM];
__device__ __nv_bfloat16 g_Xl [MAXN * IN_DIM];
__device__ __nv_bfloat16 g_AGh[MAXN * OUT_DIM];
__device__ __nv_bfloat16 g_AGl[MAXN * OUT_DIM];
__device__ __nv_bfloat16 g_Wh [4 * OUT_DIM * IN_DIM];
__device__ __nv_bfloat16 g_Wl [4 * OUT_DIM * IN_DIM];
__device__ __half g_Qh [MAXN * OUT_DIM];
__device__ __half g_KVh[MAXN * 2 * OUT_DIM];   // interleaved: [n][2d]=K, [n][2d+1]=V
__device__ int   g_deg[MAXN];
__device__ int   g_ptr[MAXN + 1];
__device__ int   g_cur[MAXN];
__device__ int   g_src[MAXE];
__device__ int   g_bsum[128];

// ---------------- asm helpers (family-common: sm_80+) -------------------------
__device__ __forceinline__ uint32_t smem_u32(const void* p) {
    uint32_t a;
    asm("{ .reg .u64 t; cvta.to.shared.u64 t, %1; cvt.u32.u64 %0, t; }"
        : "=r"(a) : "l"(p));
    return a;
}
__device__ __forceinline__ void cp16(uint32_t dst, const void* src, uint32_t bytes) {
    asm volatile("cp.async.cg.shared.global [%0], [%1], 16, %2;"
                 :: "r"(dst), "l"(src), "r"(bytes));
}
#define CP_COMMIT() asm volatile("cp.async.commit_group;" ::: "memory")
#define CP_WAIT(n)  asm volatile("cp.async.wait_group %0;" :: "n"(n) : "memory")

__device__ __forceinline__ void ldm_x4(uint32_t* r, uint32_t addr) {
    asm volatile("ldmatrix.sync.aligned.m8n8.x4.shared.b16 {%0,%1,%2,%3}, [%4];"
                 : "=r"(r[0]), "=r"(r[1]), "=r"(r[2]), "=r"(r[3]) : "r"(addr));
}
__device__ __forceinline__ void ldm_x2(uint32_t* r, uint32_t addr) {
    asm volatile("ldmatrix.sync.aligned.m8n8.x2.shared.b16 {%0,%1}, [%2];"
                 : "=r"(r[0]), "=r"(r[1]) : "r"(addr));
}
__device__ __forceinline__ void mma_bf16(float* c, const uint32_t* a, const uint32_t* b) {
    asm volatile("mma.sync.aligned.m16n8k16.row.col.f32.bf16.bf16.f32 "
                 "{%0,%1,%2,%3}, {%4,%5,%6,%7}, {%8,%9}, {%0,%1,%2,%3};"
                 : "+f"(c[0]), "+f"(c[1]), "+f"(c[2]), "+f"(c[3])
                 : "r"(a[0]), "r"(a[1]), "r"(a[2]), "r"(a[3]), "r"(b[0]), "r"(b[1]));
}

// ---------------- split-bf16 conversion kernels -------------------------------
__device__ __forceinline__ void split2(float x, float y,
                                       __nv_bfloat162& hi, __nv_bfloat162& lo) {
    __nv_bfloat16 hx = __float2bfloat16(x), hy = __float2bfloat16(y);
    __nv_bfloat16 lx = __float2bfloat16(x - __bfloat162float(hx));
    __nv_bfloat16 ly = __float2bfloat16(y - __bfloat162float(hy));
    hi = __nv_bfloat162(hx, hy);
    lo = __nv_bfloat162(lx, ly);
}
// TE (user|item concat) and x in ONE launch: i < total4 -> TE, else -> x
__global__ void cvt_split_ax_kernel(const float4* __restrict__ user,
                                    const float4* __restrict__ item,
                                    const float4* __restrict__ x,
                                    int nu4, int total4) {
    __nv_bfloat162* teh = reinterpret_cast<__nv_bfloat162*>(g_TEh);
    __nv_bfloat162* tel = reinterpret_cast<__nv_bfloat162*>(g_TEl);
    __nv_bfloat162* xh  = reinterpret_cast<__nv_bfloat162*>(g_Xh);
    __nv_bfloat162* xl  = reinterpret_cast<__nv_bfloat162*>(g_Xl);
    int tot2 = total4 * 2;
    for (int i = blockIdx.x * blockDim.x + threadIdx.x; i < tot2;
         i += gridDim.x * blockDim.x) {
        if (i < total4) {
            float4 v = (i < nu4) ? user[i] : item[i - nu4];
            split2(v.x, v.y, teh[2 * i],     tel[2 * i]);
            split2(v.z, v.w, teh[2 * i + 1], tel[2 * i + 1]);
        } else {
            int j = i - total4;
            float4 v = x[j];
            split2(v.x, v.y, xh[2 * j],     xl[2 * j]);
            split2(v.z, v.w, xh[2 * j + 1], xl[2 * j + 1]);
        }
    }
}
__global__ void cvt_split_w4_kernel(const float4* __restrict__ W0,
                                    const float4* __restrict__ W1,
                                    const float4* __restrict__ W2,
                                    const float4* __restrict__ W3) {
    __nv_bfloat162* hi = reinterpret_cast<__nv_bfloat162*>(g_Wh);
    __nv_bfloat162* lo = reinterpret_cast<__nv_bfloat162*>(g_Wl);
    const float4* Ws[4] = {W0, W1, W2, W3};
    for (int i = blockIdx.x * blockDim.x + threadIdx.x; i < 65536;
         i += gridDim.x * blockDim.x) {
        float4 v = Ws[i >> 14][i & 16383];
        split2(v.x, v.y, hi[2 * i],     lo[2 * i]);
        split2(v.z, v.w, hi[2 * i + 1], lo[2 * i + 1]);
    }
}

// ---------------- CSR build ----------------------------------------------------
__global__ void count_kernel(const int4* __restrict__ col4, int E4, int E,
                             const int* __restrict__ col) {
    int i = blockIdx.x * blockDim.x + threadIdx.x;
    for (int e = i; e < E4; e += gridDim.x * blockDim.x) {
        int4 c = col4[e];
        atomicAdd(&g_deg[c.x], 1);
        atomicAdd(&g_deg[c.y], 1);
        atomicAdd(&g_deg[c.z], 1);
        atomicAdd(&g_deg[c.w], 1);
    }
    if (i == 0)
        for (int e = E4 * 4; e < E; e++) atomicAdd(&g_deg[col[e]], 1);
}
__global__ void scan_partial_kernel(int n) {
    __shared__ int sh[1024];
    int i = blockIdx.x * 1024 + threadIdx.x;
    int v = (i < n) ? g_deg[i] : 0;
    sh[threadIdx.x] = v;
    __syncthreads();
    for (int off = 1; off < 1024; off <<= 1) {
        int t = (threadIdx.x >= off) ? sh[threadIdx.x - off] : 0;
        __syncthreads();
        sh[threadIdx.x] += t;
        __syncthreads();
    }
    if (i < n) g_ptr[i] = sh[threadIdx.x] - v;
    if (threadIdx.x == 1023) g_bsum[blockIdx.x] = sh[1023];
}
// folds block-sum prefix (<=49 values) into each thread; no separate scan launch
__global__ void scan_add_kernel(int n, int E) {
    int i = blockIdx.x * blockDim.x + threadIdx.x;
    if (i < n) {
        int nb = i >> 10;
        int base = 0;
        for (int b = 0; b < nb; b++) base += g_bsum[b];
        int p = g_ptr[i] + base;
        g_ptr[i] = p;
        g_cur[i] = p;
    }
    if (i == 0) g_ptr[n] = E;
}
__global__ void scatter_kernel(const int4* __restrict__ row4,
                               const int4* __restrict__ col4, int E4, int E,
                               const int* __restrict__ row,
                               const int* __restrict__ col) {
    int i = blockIdx.x * blockDim.x + threadIdx.x;
    for (int e = i; e < E4; e += gridDim.x * blockDim.x) {
        int4 r = row4[e];
        int4 c = col4[e];
        g_src[atomicAdd(&g_cur[c.x], 1)] = r.x;
        g_src[atomicAdd(&g_cur[c.y], 1)] = r.y;
        g_src[atomicAdd(&g_cur[c.z], 1)] = r.z;
        g_src[atomicAdd(&g_cur[c.w], 1)] = r.w;
    }
    if (i == 0)
        for (int e = E4 * 4; e < E; e++)
            g_src[atomicAdd(&g_cur[col[e]], 1)] = row[e];
}

// ---------------- 3M-split bf16 HMMA GEMM, dedup A loads -----------------------
// 8 super-tiles: t=0..3 load {Ah(kt),Wh(kt),Wl(kt)}, 2 passes (Ah*Wh, Ah*Wl);
//                t=4..7 load {Al(kt),Wh(kt)}, 1 pass (Al*Wh).
// CTA 128x128, 256 thr, 2 CTA/SM. stage = A(16K)+W0(16K)+W1(16K) = 48KB x2.
#define S_A  0
#define S_W0 16384
#define S_W1 32768
#define STG  49152
#define GEMM_SMEM (2 * STG)

__global__ void __launch_bounds__(256, 2)
gemm3m_kernel(const __nv_bfloat16* __restrict__ Ah, const __nv_bfloat16* __restrict__ Al,
              const __nv_bfloat16* __restrict__ Wh, const __nv_bfloat16* __restrict__ Wl,
              const float* __restrict__ bias, const float* __restrict__ bias2,
              float* __restrict__ C, __half* __restrict__ Ch, int cs, int cp, int M) {
    extern __shared__ char smem[];
    const uint32_t sb = smem_u32(smem);
    const int tid = threadIdx.x, wid = tid >> 5, lid = tid & 31;
    const int bm = blockIdx.x * 128;
    const int bn = blockIdx.y * 128;
    const int wm = (wid >> 2) * 64;
    const int wn = (wid & 3) * 32;

    float acc[4][4][4];
#pragma unroll
    for (int i = 0; i < 4; i++)
#pragma unroll
        for (int j = 0; j < 4; j++)
#pragma unroll
            for (int k = 0; k < 4; k++) acc[i][j][k] = 0.f;

    auto load_tile = [&](int t, int stage) {
        const bool loA = (t >= 4);
        const int koff = (t & 3) * 64;               // elements
        const __nv_bfloat16* As = loA ? Al : Ah;
        const uint32_t base = sb + stage * STG;
        // A tile
#pragma unroll
        for (int i = tid; i < 1024; i += 256) {
            int r = i >> 3, c = i & 7;
            int grow = bm + r;
            const char* g = (const char*)As + (size_t)grow * 512 + koff * 2 + c * 16;
            uint32_t d = base + S_A + r * 128 + ((c ^ (r & 7)) << 4);
            cp16(d, g, (grow < M) ? 16u : 0u);
        }
        // Wh tile (always)
#pragma unroll
        for (int i = tid; i < 1024; i += 256) {
            int r = i >> 3, c = i & 7;
            const char* g = (const char*)Wh + (size_t)(bn + r) * 512 + koff * 2 + c * 16;
            uint32_t d = base + S_W0 + r * 128 + ((c ^ (r & 7)) << 4);
            cp16(d, g, 16u);
        }
        // Wl tile (only for t<4)
        if (!loA) {
#pragma unroll
            for (int i = tid; i < 1024; i += 256) {
                int r = i >> 3, c = i & 7;
                const char* g = (const char*)Wl + (size_t)(bn + r) * 512 + koff * 2 + c * 16;
                uint32_t d = base + S_W1 + r * 128 + ((c ^ (r & 7)) << 4);
                cp16(d, g, 16u);
            }
        }
        CP_COMMIT();
    };

    load_tile(0, 0);

    for (int t = 0; t < 8; t++) {
        const int st = t & 1;
        if (t + 1 < 8) {
            load_tile(t + 1, (t + 1) & 1);
            CP_WAIT(1);
        } else {
            CP_WAIT(0);
        }
        __syncthreads();

        const uint32_t base = sb + st * STG;
        const int npass = (t < 4) ? 2 : 1;
        for (int p = 0; p < npass; p++) {
            const uint32_t aoff = base + S_A;
            const uint32_t woff = base + ((p == 0) ? S_W0 : S_W1);
#pragma unroll
            for (int ks = 0; ks < 4; ks++) {
                uint32_t a[4][4], b[4][2];
#pragma unroll
                for (int ma = 0; ma < 4; ma++) {
                    int ar = wm + ma * 16 + (lid & 15);
                    int ch = ks * 2 + (lid >> 4);
                    ldm_x4(a[ma], aoff + ar * 128 + ((ch ^ (ar & 7)) << 4));
                }
#pragma unroll
                for (int na = 0; na < 4; na++) {
                    int nr = wn + na * 8 + (lid & 7);
                    int ch = ks * 2 + ((lid >> 3) & 1);
                    ldm_x2(b[na], woff + nr * 128 + ((ch ^ (nr & 7)) << 4));
                }
#pragma unroll
                for (int ma = 0; ma < 4; ma++)
#pragma unroll
                    for (int na = 0; na < 4; na++)
                        mma_bf16(acc[ma][na], a[ma], b[na]);
            }
        }
        __syncthreads();
    }

    const int g = lid >> 2;
    const int tg = (lid & 3) * 2;
    const int cstride = OUT_DIM * cs;
#pragma unroll
    for (int ma = 0; ma < 4; ma++) {
        int mr = bm + wm + ma * 16 + g;
#pragma unroll
        for (int na = 0; na < 4; na++) {
            int nc = bn + wn + na * 8 + tg;
            float b0 = bias[nc], b1 = bias[nc + 1];
            if (bias2) { b0 += bias2[nc]; b1 += bias2[nc + 1]; }
            float o00 = acc[ma][na][0] + b0, o01 = acc[ma][na][1] + b1;
            float o10 = acc[ma][na][2] + b0, o11 = acc[ma][na][3] + b1;
            if (Ch) {
                if (cs == 1) {
                    if (mr < M)
                        *(__half2*)(Ch + (size_t)mr * OUT_DIM + nc) = __floats2half2_rn(o00, o01);
                    if (mr + 8 < M)
                        *(__half2*)(Ch + (size_t)(mr + 8) * OUT_DIM + nc) = __floats2half2_rn(o10, o11);
                } else {
                    if (mr < M) {
                        Ch[(size_t)mr * cstride + 2 * nc + cp]       = __float2half_rn(o00);
                        Ch[(size_t)mr * cstride + 2 * (nc + 1) + cp] = __float2half_rn(o01);
                    }
                    if (mr + 8 < M) {
                        Ch[(size_t)(mr + 8) * cstride + 2 * nc + cp]       = __float2half_rn(o10);
                        Ch[(size_t)(mr + 8) * cstride + 2 * (nc + 1) + cp] = __float2half_rn(o11);
                    }
                }
            } else {
                if (mr < M)
                    *(float2*)(C + (size_t)mr * OUT_DIM + nc) = make_float2(o00, o01);
                if (mr + 8 < M)
                    *(float2*)(C + (size_t)(mr + 8) * OUT_DIM + nc) = make_float2(o10, o11);
            }
        }
    }
}

// ---------------- per-node attention: 2 nodes/block, interleaved KV, 2-edge ILP
__global__ void __launch_bounds__(256)
attn_kernel(int N) {
    const int n = blockIdx.x * 2 + (threadIdx.x >> 7);
    if (n >= N) return;
    const int tid = threadIdx.x & 127;
    const int w = tid >> 5, lid = tid & 31;
    const int head = w * 2 + (lid >> 4);
    const int sl = lid & 15;
    const int h2off = head * 16 + sl;

    const int beg = g_ptr[n];
    const int end = g_ptr[n + 1];

    const __half2* Qh2 = reinterpret_cast<const __half2*>(g_Qh);
    const uint2*   KV  = reinterpret_cast<const uint2*>(g_KVh);

    const float2 qf = __half22float2(Qh2[(size_t)n * 128 + h2off]);
    const float inv_sqrt_dk = 0.17677669529663689f;

    float s = 0.f, ax = 0.f, ay = 0.f;

    int i = beg;
    for (; i + 1 < end; i += 2) {
        int r0 = g_src[i], r1 = g_src[i + 1];
        uint2 kv0 = KV[(size_t)r0 * 128 + h2off];
        uint2 kv1 = KV[(size_t)r1 * 128 + h2off];
        float2 a0 = __half22float2(*(__half2*)&kv0.x);
        float2 b0 = __half22float2(*(__half2*)&kv0.y);
        float2 a1 = __half22float2(*(__half2*)&kv1.x);
        float2 b1 = __half22float2(*(__half2*)&kv1.y);
        float p0 = qf.x * a0.x + qf.y * b0.x;
        float p1 = qf.x * a1.x + qf.y * b1.x;
        p0 += __shfl_xor_sync(0xffffffffu, p0, 8);
        p1 += __shfl_xor_sync(0xffffffffu, p1, 8);
        p0 += __shfl_xor_sync(0xffffffffu, p0, 4);
        p1 += __shfl_xor_sync(0xffffffffu, p1, 4);
        p0 += __shfl_xor_sync(0xffffffffu, p0, 2);
        p1 += __shfl_xor_sync(0xffffffffu, p1, 2);
        p0 += __shfl_xor_sync(0xffffffffu, p0, 1);
        p1 += __shfl_xor_sync(0xffffffffu, p1, 1);
        float e0 = __expf(p0 * inv_sqrt_dk);
        float e1 = __expf(p1 * inv_sqrt_dk);
        s += e0 + e1;
        ax += e0 * a0.y + e1 * a1.y;
        ay += e0 * b0.y + e1 * b1.y;
    }
    if (i < end) {
        int r0 = g_src[i];
        uint2 kv0 = KV[(size_t)r0 * 128 + h2off];
        float2 a0 = __half22float2(*(__half2*)&kv0.x);
        float2 b0 = __half22float2(*(__half2*)&kv0.y);
        float p0 = qf.x * a0.x + qf.y * b0.x;
        p0 += __shfl_xor_sync(0xffffffffu, p0, 8);
        p0 += __shfl_xor_sync(0xffffffffu, p0, 4);
        p0 += __shfl_xor_sync(0xffffffffu, p0, 2);
        p0 += __shfl_xor_sync(0xffffffffu, p0, 1);
        float e0 = __expf(p0 * inv_sqrt_dk);
        s += e0;
        ax += e0 * a0.y;
        ay += e0 * b0.y;
    }

    float ox = 0.f, oy = 0.f;
    if (s > 0.f) { float inv = 1.f / s; ox = ax * inv; oy = ay * inv; }
    __nv_bfloat162 hi, lo;
    split2(ox, oy, hi, lo);
    reinterpret_cast<__nv_bfloat162*>(g_AGh)[(size_t)n * 128 + h2off] = hi;
    reinterpret_cast<__nv_bfloat162*>(g_AGl)[(size_t)n * 128 + h2off] = lo;
}

// ---------------- launch --------------------------------------------------------
extern "C" void kernel_launch(void* const* d_in, const int* in_sizes, int n_in,
                              void* d_out, int out_size) {
    const float* x    = (const float*)d_in[0];
    const int*   row  = (const int*)  d_in[1];
    const int*   col  = (const int*)  d_in[2];
    const float* rel  = (const float*)d_in[3];
    const float* user = (const float*)d_in[4];
    const float* item = (const float*)d_in[5];
    const float* Wq   = (const float*)d_in[6];
    const float* bq   = (const float*)d_in[7];
    const float* Wk   = (const float*)d_in[8];
    const float* bk   = (const float*)d_in[9];
    const float* Wv   = (const float*)d_in[10];
    const float* bv   = (const float*)d_in[11];
    const float* Wo   = (const float*)d_in[12];
    const float* bo   = (const float*)d_in[13];
    float* out = (float*)d_out;

    const int N  = in_sizes[0] / IN_DIM;
    const int E  = in_sizes[1];
    const int NU = in_sizes[4] / IN_DIM;
    const int E4 = E >> 2;

    __half *dQh, *dKVh;
    __nv_bfloat16 *dTEh, *dTEl, *dXh, *dXl, *dAGh, *dAGl, *dWh, *dWl;
    int* dDeg;
    cudaGetSymbolAddress((void**)&dQh,  g_Qh);
    cudaGetSymbolAddress((void**)&dKVh, g_KVh);
    cudaGetSymbolAddress((void**)&dTEh, g_TEh);
    cudaGetSymbolAddress((void**)&dTEl, g_TEl);
    cudaGetSymbolAddress((void**)&dXh,  g_Xh);
    cudaGetSymbolAddress((void**)&dXl,  g_Xl);
    cudaGetSymbolAddress((void**)&dAGh, g_AGh);
    cudaGetSymbolAddress((void**)&dAGl, g_AGl);
    cudaGetSymbolAddress((void**)&dWh,  g_Wh);
    cudaGetSymbolAddress((void**)&dWl,  g_Wl);
    cudaGetSymbolAddress((void**)&dDeg, g_deg);

    cudaFuncSetAttribute(gemm3m_kernel,
                         cudaFuncAttributeMaxDynamicSharedMemorySize, GEMM_SMEM);

    // 1. split-bf16 conversions (2 launches)
    {
        int total4 = N * (IN_DIM / 4);
        int nu4 = NU * (IN_DIM / 4);
        cvt_split_ax_kernel<<<2048, 256>>>((const float4*)user, (const float4*)item,
                                           (const float4*)x, nu4, total4);
        cvt_split_w4_kernel<<<256, 256>>>((const float4*)Wq, (const float4*)Wk,
                                          (const float4*)Wv, (const float4*)Wo);
    }

    // 2. CSR build by destination (col)
    cudaMemsetAsync(dDeg, 0, (size_t)N * sizeof(int), 0);
    count_kernel<<<(E4 + 255) / 256, 256>>>((const int4*)col, E4, E, col);
    int nb = (N + 1023) / 1024;
    scan_partial_kernel<<<nb, 1024>>>(N);
    scan_add_kernel<<<(N + 255) / 256, 256>>>(N, E);
    scatter_kernel<<<(E4 + 255) / 256, 256>>>((const int4*)row, (const int4*)col,
                                              E4, E, row, col);

    // 3. projections -> fp16 (Q dense; Kr/V interleaved into g_KVh)
    dim3 gg((N + 127) / 128, 2);
    gemm3m_kernel<<<gg, 256, GEMM_SMEM>>>(dTEh, dTEl, dWh + 0 * 65536, dWl + 0 * 65536,
                                          bq, nullptr, nullptr, dQh, 1, 0, N);
    gemm3m_kernel<<<gg, 256, GEMM_SMEM>>>(dTEh, dTEl, dWh + 1 * 65536, dWl + 1 * 65536,
                                          bk, rel,     nullptr, dKVh, 2, 0, N);
    gemm3m_kernel<<<gg, 256, GEMM_SMEM>>>(dXh,  dXl,  dWh + 2 * 65536, dWl + 2 * 65536,
                                          bv, nullptr, nullptr, dKVh, 2, 1, N);

    // 4. attention
    attn_kernel<<<(N + 1) / 2, 256>>>(N);

    // 5. output projection -> fp32 out
    gemm3m_kernel<<<gg, 256, GEMM_SMEM>>>(dAGh, dAGl, dWh + 3 * 65536, dWl + 3 * 65536,
                                          bo, nullptr, out, nullptr, 1, 0, N);
}

// round 11
// speedup vs baseline: 1.8782x; 1.4090x over previous
#include <cuda_runtime.h>
#include <cuda_bf16.h>
#include <cuda_fp16.h>
#include <math.h>
#include <stdint.h>

#define IN_DIM 256
#define OUT_DIM 256
#define DK 32
#define MAXN 50000
#define MAXE 800000

// ---------------- static device scratch (no cudaMalloc anywhere) ------------
__device__ __half g_TE [MAXN * IN_DIM];        // concat(user,item) fp16
__device__ __half g_X  [MAXN * IN_DIM];        // x fp16
__device__ __half g_AG [MAXN * OUT_DIM];       // attention output fp16
__device__ __half g_W  [4 * OUT_DIM * IN_DIM]; // Wq,Wk,Wv,Wo fp16
__device__ __half g_Qh [MAXN * OUT_DIM];
__device__ __half g_KVh[MAXN * 2 * OUT_DIM];   // interleaved: [n][2d]=K, [n][2d+1]=V
__device__ int   g_deg[MAXN];
__device__ int   g_ptr[MAXN + 1];
__device__ int   g_cur[MAXN];
__device__ int   g_src[MAXE];
__device__ int   g_bsum[128];

// ---------------- asm helpers (family-common: sm_80+) -------------------------
__device__ __forceinline__ uint32_t smem_u32(const void* p) {
    uint32_t a;
    asm("{ .reg .u64 t; cvta.to.shared.u64 t, %1; cvt.u32.u64 %0, t; }"
        : "=r"(a) : "l"(p));
    return a;
}
__device__ __forceinline__ void cp16(uint32_t dst, const void* src, uint32_t bytes) {
    asm volatile("cp.async.cg.shared.global [%0], [%1], 16, %2;"
                 :: "r"(dst), "l"(src), "r"(bytes));
}
#define CP_COMMIT() asm volatile("cp.async.commit_group;" ::: "memory")
#define CP_WAIT(n)  asm volatile("cp.async.wait_group %0;" :: "n"(n) : "memory")

__device__ __forceinline__ void ldm_x4(uint32_t* r, uint32_t addr) {
    asm volatile("ldmatrix.sync.aligned.m8n8.x4.shared.b16 {%0,%1,%2,%3}, [%4];"
                 : "=r"(r[0]), "=r"(r[1]), "=r"(r[2]), "=r"(r[3]) : "r"(addr));
}
__device__ __forceinline__ void ldm_x2(uint32_t* r, uint32_t addr) {
    asm volatile("ldmatrix.sync.aligned.m8n8.x2.shared.b16 {%0,%1}, [%2];"
                 : "=r"(r[0]), "=r"(r[1]) : "r"(addr));
}
__device__ __forceinline__ void mma_f16(float* c, const uint32_t* a, const uint32_t* b) {
    asm volatile("mma.sync.aligned.m16n8k16.row.col.f32.f16.f16.f32 "
                 "{%0,%1,%2,%3}, {%4,%5,%6,%7}, {%8,%9}, {%0,%1,%2,%3};"
                 : "+f"(c[0]), "+f"(c[1]), "+f"(c[2]), "+f"(c[3])
                 : "r"(a[0]), "r"(a[1]), "r"(a[2]), "r"(a[3]), "r"(b[0]), "r"(b[1]));
}

// ---------------- fp16 conversion kernels -------------------------------------
// TE (user|item concat) and x in ONE launch
__global__ void cvt_ax_kernel(const float4* __restrict__ user,
                              const float4* __restrict__ item,
                              const float4* __restrict__ x,
                              int nu4, int total4) {
    __half2* te = reinterpret_cast<__half2*>(g_TE);
    __half2* xx = reinterpret_cast<__half2*>(g_X);
    int tot2 = total4 * 2;
    for (int i = blockIdx.x * blockDim.x + threadIdx.x; i < tot2;
         i += gridDim.x * blockDim.x) {
        if (i < total4) {
            float4 v = (i < nu4) ? user[i] : item[i - nu4];
            te[2 * i]     = __floats2half2_rn(v.x, v.y);
            te[2 * i + 1] = __floats2half2_rn(v.z, v.w);
        } else {
            int j = i - total4;
            float4 v = x[j];
            xx[2 * j]     = __floats2half2_rn(v.x, v.y);
            xx[2 * j + 1] = __floats2half2_rn(v.z, v.w);
        }
    }
}
__global__ void cvt_w4_kernel(const float4* __restrict__ W0,
                              const float4* __restrict__ W1,
                              const float4* __restrict__ W2,
                              const float4* __restrict__ W3) {
    __half2* dst = reinterpret_cast<__half2*>(g_W);
    const float4* Ws[4] = {W0, W1, W2, W3};
    for (int i = blockIdx.x * blockDim.x + threadIdx.x; i < 65536;
         i += gridDim.x * blockDim.x) {
        float4 v = Ws[i >> 14][i & 16383];
        dst[2 * i]     = __floats2half2_rn(v.x, v.y);
        dst[2 * i + 1] = __floats2half2_rn(v.z, v.w);
    }
}

// ---------------- CSR build ----------------------------------------------------
__global__ void count_kernel(const int4* __restrict__ col4, int E4, int E,
                             const int* __restrict__ col) {
    int i = blockIdx.x * blockDim.x + threadIdx.x;
    for (int e = i; e < E4; e += gridDim.x * blockDim.x) {
        int4 c = col4[e];
        atomicAdd(&g_deg[c.x], 1);
        atomicAdd(&g_deg[c.y], 1);
        atomicAdd(&g_deg[c.z], 1);
        atomicAdd(&g_deg[c.w], 1);
    }
    if (i == 0)
        for (int e = E4 * 4; e < E; e++) atomicAdd(&g_deg[col[e]], 1);
}
__global__ void scan_partial_kernel(int n) {
    __shared__ int sh[1024];
    int i = blockIdx.x * 1024 + threadIdx.x;
    int v = (i < n) ? g_deg[i] : 0;
    sh[threadIdx.x] = v;
    __syncthreads();
    for (int off = 1; off < 1024; off <<= 1) {
        int t = (threadIdx.x >= off) ? sh[threadIdx.x - off] : 0;
        __syncthreads();
        sh[threadIdx.x] += t;
        __syncthreads();
    }
    if (i < n) g_ptr[i] = sh[threadIdx.x] - v;
    if (threadIdx.x == 1023) g_bsum[blockIdx.x] = sh[1023];
}
__global__ void scan_add_kernel(int n, int E) {
    int i = blockIdx.x * blockDim.x + threadIdx.x;
    if (i < n) {
        int nb = i >> 10;
        int base = 0;
        for (int b = 0; b < nb; b++) base += g_bsum[b];
        int p = g_ptr[i] + base;
        g_ptr[i] = p;
        g_cur[i] = p;
    }
    if (i == 0) g_ptr[n] = E;
}
__global__ void scatter_kernel(const int4* __restrict__ row4,
                               const int4* __restrict__ col4, int E4, int E,
                               const int* __restrict__ row,
                               const int* __restrict__ col) {
    int i = blockIdx.x * blockDim.x + threadIdx.x;
    for (int e = i; e < E4; e += gridDim.x * blockDim.x) {
        int4 r = row4[e];
        int4 c = col4[e];
        g_src[atomicAdd(&g_cur[c.x], 1)] = r.x;
        g_src[atomicAdd(&g_cur[c.y], 1)] = r.y;
        g_src[atomicAdd(&g_cur[c.z], 1)] = r.z;
        g_src[atomicAdd(&g_cur[c.w], 1)] = r.w;
    }
    if (i == 0)
        for (int e = E4 * 4; e < E; e++)
            g_src[atomicAdd(&g_cur[col[e]], 1)] = row[e];
}

// ---------------- fp16 HMMA GEMM (single pass, K=256 in 4 k-tiles) ------------
// CTA 128x128, 256 thr, 2 CTA/SM. Stage = A(16K)+W(16K) = 32KB x2 = 64KB.
#define S_A  0
#define S_W  16384
#define STG  32768
#define GEMM_SMEM (2 * STG)

__global__ void __launch_bounds__(256, 2)
gemm_f16_kernel(const __half* __restrict__ A, const __half* __restrict__ W,
                const float* __restrict__ bias, const float* __restrict__ bias2,
                float* __restrict__ C, __half* __restrict__ Ch, int cs, int cp, int M) {
    extern __shared__ char smem[];
    const uint32_t sb = smem_u32(smem);
    const int tid = threadIdx.x, wid = tid >> 5, lid = tid & 31;
    const int bm = blockIdx.x * 128;
    const int bn = blockIdx.y * 128;
    const int wm = (wid >> 2) * 64;
    const int wn = (wid & 3) * 32;

    float acc[4][4][4];
#pragma unroll
    for (int i = 0; i < 4; i++)
#pragma unroll
        for (int j = 0; j < 4; j++)
#pragma unroll
            for (int k = 0; k < 4; k++) acc[i][j][k] = 0.f;

    auto load_tile = [&](int kt, int stage) {
        const int koff = kt * 64;                    // elements
        const uint32_t base = sb + stage * STG;
#pragma unroll
        for (int i = tid; i < 1024; i += 256) {
            int r = i >> 3, c = i & 7;
            int grow = bm + r;
            const char* g = (const char*)A + (size_t)grow * 512 + koff * 2 + c * 16;
            uint32_t d = base + S_A + r * 128 + ((c ^ (r & 7)) << 4);
            cp16(d, g, (grow < M) ? 16u : 0u);
        }
#pragma unroll
        for (int i = tid; i < 1024; i += 256) {
            int r = i >> 3, c = i & 7;
            const char* g = (const char*)W + (size_t)(bn + r) * 512 + koff * 2 + c * 16;
            uint32_t d = base + S_W + r * 128 + ((c ^ (r & 7)) << 4);
            cp16(d, g, 16u);
        }
        CP_COMMIT();
    };

    load_tile(0, 0);

#pragma unroll
    for (int t = 0; t < 4; t++) {
        const int st = t & 1;
        if (t + 1 < 4) {
            load_tile(t + 1, (t + 1) & 1);
            CP_WAIT(1);
        } else {
            CP_WAIT(0);
        }
        __syncthreads();

        const uint32_t base = sb + st * STG;
#pragma unroll
        for (int ks = 0; ks < 4; ks++) {
            uint32_t a[4][4], b[4][2];
#pragma unroll
            for (int ma = 0; ma < 4; ma++) {
                int ar = wm + ma * 16 + (lid & 15);
                int ch = ks * 2 + (lid >> 4);
                ldm_x4(a[ma], base + S_A + ar * 128 + ((ch ^ (ar & 7)) << 4));
            }
#pragma unroll
            for (int na = 0; na < 4; na++) {
                int nr = wn + na * 8 + (lid & 7);
                int ch = ks * 2 + ((lid >> 3) & 1);
                ldm_x2(b[na], base + S_W + nr * 128 + ((ch ^ (nr & 7)) << 4));
            }
#pragma unroll
            for (int ma = 0; ma < 4; ma++)
#pragma unroll
                for (int na = 0; na < 4; na++)
                    mma_f16(acc[ma][na], a[ma], b[na]);
        }
        __syncthreads();
    }

    const int g = lid >> 2;
    const int tg = (lid & 3) * 2;
    const int cstride = OUT_DIM * cs;
#pragma unroll
    for (int ma = 0; ma < 4; ma++) {
        int mr = bm + wm + ma * 16 + g;
#pragma unroll
        for (int na = 0; na < 4; na++) {
            int nc = bn + wn + na * 8 + tg;
            float b0 = bias[nc], b1 = bias[nc + 1];
            if (bias2) { b0 += bias2[nc]; b1 += bias2[nc + 1]; }
            float o00 = acc[ma][na][0] + b0, o01 = acc[ma][na][1] + b1;
            float o10 = acc[ma][na][2] + b0, o11 = acc[ma][na][3] + b1;
            if (Ch) {
                if (cs == 1) {
                    if (mr < M)
                        *(__half2*)(Ch + (size_t)mr * OUT_DIM + nc) = __floats2half2_rn(o00, o01);
                    if (mr + 8 < M)
                        *(__half2*)(Ch + (size_t)(mr + 8) * OUT_DIM + nc) = __floats2half2_rn(o10, o11);
                } else {
                    if (mr < M) {
                        Ch[(size_t)mr * cstride + 2 * nc + cp]       = __float2half_rn(o00);
                        Ch[(size_t)mr * cstride + 2 * (nc + 1) + cp] = __float2half_rn(o01);
                    }
                    if (mr + 8 < M) {
                        Ch[(size_t)(mr + 8) * cstride + 2 * nc + cp]       = __float2half_rn(o10);
                        Ch[(size_t)(mr + 8) * cstride + 2 * (nc + 1) + cp] = __float2half_rn(o11);
                    }
                }
            } else {
                if (mr < M)
                    *(float2*)(C + (size_t)mr * OUT_DIM + nc) = make_float2(o00, o01);
                if (mr + 8 < M)
                    *(float2*)(C + (size_t)(mr + 8) * OUT_DIM + nc) = make_float2(o10, o11);
            }
        }
    }
}

// ---------------- per-node attention: 2 nodes/block, interleaved KV, 2-edge ILP
__global__ void __launch_bounds__(256)
attn_kernel(int N) {
    const int n = blockIdx.x * 2 + (threadIdx.x >> 7);
    if (n >= N) return;
    const int tid = threadIdx.x & 127;
    const int w = tid >> 5, lid = tid & 31;
    const int head = w * 2 + (lid >> 4);
    const int sl = lid & 15;
    const int h2off = head * 16 + sl;

    const int beg = g_ptr[n];
    const int end = g_ptr[n + 1];

    const __half2* Qh2 = reinterpret_cast<const __half2*>(g_Qh);
    const uint2*   KV  = reinterpret_cast<const uint2*>(g_KVh);

    const float2 qf = __half22float2(Qh2[(size_t)n * 128 + h2off]);
    const float inv_sqrt_dk = 0.17677669529663689f;

    float s = 0.f, ax = 0.f, ay = 0.f;

    int i = beg;
    for (; i + 1 < end; i += 2) {
        int r0 = g_src[i], r1 = g_src[i + 1];
        uint2 kv0 = KV[(size_t)r0 * 128 + h2off];
        uint2 kv1 = KV[(size_t)r1 * 128 + h2off];
        float2 a0 = __half22float2(*(__half2*)&kv0.x);
        float2 b0 = __half22float2(*(__half2*)&kv0.y);
        float2 a1 = __half22float2(*(__half2*)&kv1.x);
        float2 b1 = __half22float2(*(__half2*)&kv1.y);
        float p0 = qf.x * a0.x + qf.y * b0.x;
        float p1 = qf.x * a1.x + qf.y * b1.x;
        p0 += __shfl_xor_sync(0xffffffffu, p0, 8);
        p1 += __shfl_xor_sync(0xffffffffu, p1, 8);
        p0 += __shfl_xor_sync(0xffffffffu, p0, 4);
        p1 += __shfl_xor_sync(0xffffffffu, p1, 4);
        p0 += __shfl_xor_sync(0xffffffffu, p0, 2);
        p1 += __shfl_xor_sync(0xffffffffu, p1, 2);
        p0 += __shfl_xor_sync(0xffffffffu, p0, 1);
        p1 += __shfl_xor_sync(0xffffffffu, p1, 1);
        float e0 = __expf(p0 * inv_sqrt_dk);
        float e1 = __expf(p1 * inv_sqrt_dk);
        s += e0 + e1;
        ax += e0 * a0.y + e1 * a1.y;
        ay += e0 * b0.y + e1 * b1.y;
    }
    if (i < end) {
        int r0 = g_src[i];
        uint2 kv0 = KV[(size_t)r0 * 128 + h2off];
        float2 a0 = __half22float2(*(__half2*)&kv0.x);
        float2 b0 = __half22float2(*(__half2*)&kv0.y);
        float p0 = qf.x * a0.x + qf.y * b0.x;
        p0 += __shfl_xor_sync(0xffffffffu, p0, 8);
        p0 += __shfl_xor_sync(0xffffffffu, p0, 4);
        p0 += __shfl_xor_sync(0xffffffffu, p0, 2);
        p0 += __shfl_xor_sync(0xffffffffu, p0, 1);
        float e0 = __expf(p0 * inv_sqrt_dk);
        s += e0;
        ax += e0 * a0.y;
        ay += e0 * b0.y;
    }

    float ox = 0.f, oy = 0.f;
    if (s > 0.f) { float inv = 1.f / s; ox = ax * inv; oy = ay * inv; }
    reinterpret_cast<__half2*>(g_AG)[(size_t)n * 128 + h2off] = __floats2half2_rn(ox, oy);
}

// ---------------- launch --------------------------------------------------------
extern "C" void kernel_launch(void* const* d_in, const int* in_sizes, int n_in,
                              void* d_out, int out_size) {
    const float* x    = (const float*)d_in[0];
    const int*   row  = (const int*)  d_in[1];
    const int*   col  = (const int*)  d_in[2];
    const float* rel  = (const float*)d_in[3];
    const float* user = (const float*)d_in[4];
    const float* item = (const float*)d_in[5];
    const float* Wq   = (const float*)d_in[6];
    const float* bq   = (const float*)d_in[7];
    const float* Wk   = (const float*)d_in[8];
    const float* bk   = (const float*)d_in[9];
    const float* Wv   = (const float*)d_in[10];
    const float* bv   = (const float*)d_in[11];
    const float* Wo   = (const float*)d_in[12];
    const float* bo   = (const float*)d_in[13];
    float* out = (float*)d_out;

    const int N  = in_sizes[0] / IN_DIM;
    const int E  = in_sizes[1];
    const int NU = in_sizes[4] / IN_DIM;
    const int E4 = E >> 2;

    __half *dQh, *dKVh, *dTE, *dX, *dAG, *dW;
    int* dDeg;
    cudaGetSymbolAddress((void**)&dQh,  g_Qh);
    cudaGetSymbolAddress((void**)&dKVh, g_KVh);
    cudaGetSymbolAddress((void**)&dTE,  g_TE);
    cudaGetSymbolAddress((void**)&dX,   g_X);
    cudaGetSymbolAddress((void**)&dAG,  g_AG);
    cudaGetSymbolAddress((void**)&dW,   g_W);
    cudaGetSymbolAddress((void**)&dDeg, g_deg);

    cudaFuncSetAttribute(gemm_f16_kernel,
                         cudaFuncAttributeMaxDynamicSharedMemorySize, GEMM_SMEM);

    // 1. fp16 conversions (2 launches)
    {
        int total4 = N * (IN_DIM / 4);
        int nu4 = NU * (IN_DIM / 4);
        cvt_ax_kernel<<<2048, 256>>>((const float4*)user, (const float4*)item,
                                     (const float4*)x, nu4, total4);
        cvt_w4_kernel<<<256, 256>>>((const float4*)Wq, (const float4*)Wk,
                                    (const float4*)Wv, (const float4*)Wo);
    }

    // 2. CSR build by destination (col)
    cudaMemsetAsync(dDeg, 0, (size_t)N * sizeof(int), 0);
    count_kernel<<<(E4 + 255) / 256, 256>>>((const int4*)col, E4, E, col);
    int nb = (N + 1023) / 1024;
    scan_partial_kernel<<<nb, 1024>>>(N);
    scan_add_kernel<<<(N + 255) / 256, 256>>>(N, E);
    scatter_kernel<<<(E4 + 255) / 256, 256>>>((const int4*)row, (const int4*)col,
                                              E4, E, row, col);

    // 3. projections (single-pass fp16 HMMA) -> fp16 intermediates
    dim3 gg((N + 127) / 128, 2);
    gemm_f16_kernel<<<gg, 256, GEMM_SMEM>>>(dTE, dW + 0 * 65536, bq, nullptr,
                                            nullptr, dQh, 1, 0, N);
    gemm_f16_kernel<<<gg, 256, GEMM_SMEM>>>(dTE, dW + 1 * 65536, bk, rel,
                                            nullptr, dKVh, 2, 0, N);
    gemm_f16_kernel<<<gg, 256, GEMM_SMEM>>>(dX,  dW + 2 * 65536, bv, nullptr,
                                            nullptr, dKVh, 2, 1, N);

    // 4. attention
    attn_kernel<<<(N + 1) / 2, 256>>>(N);

    // 5. output projection -> fp32 out
    gemm_f16_kernel<<<gg, 256, GEMM_SMEM>>>(dAG, dW + 3 * 65536, bo, nullptr,
                                            out, nullptr, 1, 0, N);
}

// round 12
// speedup vs baseline: 2.1062x; 1.1214x over previous
#include <cuda_runtime.h>
#include <cuda_bf16.h>
#include <cuda_fp16.h>
#include <math.h>
#include <stdint.h>

#define IN_DIM 256
#define OUT_DIM 256
#define DK 32
#define MAXN 50000
#define MAXE 800000

// ---------------- static device scratch (no cudaMalloc anywhere) ------------
__device__ __half g_TE [MAXN * IN_DIM];        // concat(user,item) fp16
__device__ __half g_X  [MAXN * IN_DIM];        // x fp16
__device__ __half g_AG [MAXN * OUT_DIM];       // attention output fp16
__device__ __half g_W  [4 * OUT_DIM * IN_DIM]; // Wq,Wk,Wv,Wo fp16
__device__ __half g_Qh [MAXN * OUT_DIM];
__device__ __half g_KVh[MAXN * 2 * OUT_DIM];   // interleaved: [n][2d]=K, [n][2d+1]=V
__device__ int   g_deg[MAXN];
__device__ int   g_ptr[MAXN + 1];
__device__ int   g_cur[MAXN];
__device__ int   g_src[MAXE];
__device__ int   g_bsum[128];

// ---------------- asm helpers (family-common: sm_80+) -------------------------
__device__ __forceinline__ uint32_t smem_u32(const void* p) {
    uint32_t a;
    asm("{ .reg .u64 t; cvta.to.shared.u64 t, %1; cvt.u32.u64 %0, t; }"
        : "=r"(a) : "l"(p));
    return a;
}
__device__ __forceinline__ void cp16(uint32_t dst, const void* src, uint32_t bytes) {
    asm volatile("cp.async.cg.shared.global [%0], [%1], 16, %2;"
                 :: "r"(dst), "l"(src), "r"(bytes));
}
#define CP_COMMIT() asm volatile("cp.async.commit_group;" ::: "memory")
#define CP_WAIT(n)  asm volatile("cp.async.wait_group %0;" :: "n"(n) : "memory")

__device__ __forceinline__ void ldm_x4(uint32_t* r, uint32_t addr) {
    asm volatile("ldmatrix.sync.aligned.m8n8.x4.shared.b16 {%0,%1,%2,%3}, [%4];"
                 : "=r"(r[0]), "=r"(r[1]), "=r"(r[2]), "=r"(r[3]) : "r"(addr));
}
__device__ __forceinline__ void ldm_x2(uint32_t* r, uint32_t addr) {
    asm volatile("ldmatrix.sync.aligned.m8n8.x2.shared.b16 {%0,%1}, [%2];"
                 : "=r"(r[0]), "=r"(r[1]) : "r"(addr));
}
__device__ __forceinline__ void mma_f16(float* c, const uint32_t* a, const uint32_t* b) {
    asm volatile("mma.sync.aligned.m16n8k16.row.col.f32.f16.f16.f32 "
                 "{%0,%1,%2,%3}, {%4,%5,%6,%7}, {%8,%9}, {%0,%1,%2,%3};"
                 : "+f"(c[0]), "+f"(c[1]), "+f"(c[2]), "+f"(c[3])
                 : "r"(a[0]), "r"(a[1]), "r"(a[2]), "r"(a[3]), "r"(b[0]), "r"(b[1]));
}

// ---------------- fp16 conversion kernels -------------------------------------
__global__ void cvt_ax_kernel(const float4* __restrict__ user,
                              const float4* __restrict__ item,
                              const float4* __restrict__ x,
                              int nu4, int total4) {
    __half2* te = reinterpret_cast<__half2*>(g_TE);
    __half2* xx = reinterpret_cast<__half2*>(g_X);
    int tot2 = total4 * 2;
    for (int i = blockIdx.x * blockDim.x + threadIdx.x; i < tot2;
         i += gridDim.x * blockDim.x) {
        if (i < total4) {
            float4 v = (i < nu4) ? user[i] : item[i - nu4];
            te[2 * i]     = __floats2half2_rn(v.x, v.y);
            te[2 * i + 1] = __floats2half2_rn(v.z, v.w);
        } else {
            int j = i - total4;
            float4 v = x[j];
            xx[2 * j]     = __floats2half2_rn(v.x, v.y);
            xx[2 * j + 1] = __floats2half2_rn(v.z, v.w);
        }
    }
}
__global__ void cvt_w4_kernel(const float4* __restrict__ W0,
                              const float4* __restrict__ W1,
                              const float4* __restrict__ W2,
                              const float4* __restrict__ W3) {
    __half2* dst = reinterpret_cast<__half2*>(g_W);
    const float4* Ws[4] = {W0, W1, W2, W3};
    for (int i = blockIdx.x * blockDim.x + threadIdx.x; i < 65536;
         i += gridDim.x * blockDim.x) {
        float4 v = Ws[i >> 14][i & 16383];
        dst[2 * i]     = __floats2half2_rn(v.x, v.y);
        dst[2 * i + 1] = __floats2half2_rn(v.z, v.w);
    }
}

// ---------------- CSR build ----------------------------------------------------
__global__ void count_kernel(const int4* __restrict__ col4, int E4, int E,
                             const int* __restrict__ col) {
    int i = blockIdx.x * blockDim.x + threadIdx.x;
    for (int e = i; e < E4; e += gridDim.x * blockDim.x) {
        int4 c = col4[e];
        atomicAdd(&g_deg[c.x], 1);
        atomicAdd(&g_deg[c.y], 1);
        atomicAdd(&g_deg[c.z], 1);
        atomicAdd(&g_deg[c.w], 1);
    }
    if (i == 0)
        for (int e = E4 * 4; e < E; e++) atomicAdd(&g_deg[col[e]], 1);
}
__global__ void scan_partial_kernel(int n) {
    __shared__ int sh[1024];
    int i = blockIdx.x * 1024 + threadIdx.x;
    int v = (i < n) ? g_deg[i] : 0;
    sh[threadIdx.x] = v;
    __syncthreads();
    for (int off = 1; off < 1024; off <<= 1) {
        int t = (threadIdx.x >= off) ? sh[threadIdx.x - off] : 0;
        __syncthreads();
        sh[threadIdx.x] += t;
        __syncthreads();
    }
    if (i < n) g_ptr[i] = sh[threadIdx.x] - v;
    if (threadIdx.x == 1023) g_bsum[blockIdx.x] = sh[1023];
}
__global__ void scan_add_kernel(int n, int E) {
    int i = blockIdx.x * blockDim.x + threadIdx.x;
    if (i < n) {
        int nb = i >> 10;
        int base = 0;
        for (int b = 0; b < nb; b++) base += g_bsum[b];
        int p = g_ptr[i] + base;
        g_ptr[i] = p;
        g_cur[i] = p;
    }
    if (i == 0) g_ptr[n] = E;
}
__global__ void scatter_kernel(const int4* __restrict__ row4,
                               const int4* __restrict__ col4, int E4, int E,
                               const int* __restrict__ row,
                               const int* __restrict__ col) {
    int i = blockIdx.x * blockDim.x + threadIdx.x;
    for (int e = i; e < E4; e += gridDim.x * blockDim.x) {
        int4 r = row4[e];
        int4 c = col4[e];
        g_src[atomicAdd(&g_cur[c.x], 1)] = r.x;
        g_src[atomicAdd(&g_cur[c.y], 1)] = r.y;
        g_src[atomicAdd(&g_cur[c.z], 1)] = r.z;
        g_src[atomicAdd(&g_cur[c.w], 1)] = r.w;
    }
    if (i == 0)
        for (int e = E4 * 4; e < E; e++)
            g_src[atomicAdd(&g_cur[col[e]], 1)] = row[e];
}

// ---------------- fp16 HMMA GEMM (single pass, K=256 in 4 k-tiles) ------------
#define S_A  0
#define S_W  16384
#define STG  32768
#define GEMM_SMEM (2 * STG)

__global__ void __launch_bounds__(256, 2)
gemm_f16_kernel(const __half* __restrict__ A, const __half* __restrict__ W,
                const float* __restrict__ bias, const float* __restrict__ bias2,
                float* __restrict__ C, __half* __restrict__ Ch, int cs, int cp, int M) {
    extern __shared__ char smem[];
    const uint32_t sb = smem_u32(smem);
    const int tid = threadIdx.x, wid = tid >> 5, lid = tid & 31;
    const int bm = blockIdx.x * 128;
    const int bn = blockIdx.y * 128;
    const int wm = (wid >> 2) * 64;
    const int wn = (wid & 3) * 32;

    float acc[4][4][4];
#pragma unroll
    for (int i = 0; i < 4; i++)
#pragma unroll
        for (int j = 0; j < 4; j++)
#pragma unroll
            for (int k = 0; k < 4; k++) acc[i][j][k] = 0.f;

    auto load_tile = [&](int kt, int stage) {
        const int koff = kt * 64;
        const uint32_t base = sb + stage * STG;
#pragma unroll
        for (int i = tid; i < 1024; i += 256) {
            int r = i >> 3, c = i & 7;
            int grow = bm + r;
            const char* g = (const char*)A + (size_t)grow * 512 + koff * 2 + c * 16;
            uint32_t d = base + S_A + r * 128 + ((c ^ (r & 7)) << 4);
            cp16(d, g, (grow < M) ? 16u : 0u);
        }
#pragma unroll
        for (int i = tid; i < 1024; i += 256) {
            int r = i >> 3, c = i & 7;
            const char* g = (const char*)W + (size_t)(bn + r) * 512 + koff * 2 + c * 16;
            uint32_t d = base + S_W + r * 128 + ((c ^ (r & 7)) << 4);
            cp16(d, g, 16u);
        }
        CP_COMMIT();
    };

    load_tile(0, 0);

#pragma unroll
    for (int t = 0; t < 4; t++) {
        const int st = t & 1;
        if (t + 1 < 4) {
            load_tile(t + 1, (t + 1) & 1);
            CP_WAIT(1);
        } else {
            CP_WAIT(0);
        }
        __syncthreads();

        const uint32_t base = sb + st * STG;
#pragma unroll
        for (int ks = 0; ks < 4; ks++) {
            uint32_t a[4][4], b[4][2];
#pragma unroll
            for (int ma = 0; ma < 4; ma++) {
                int ar = wm + ma * 16 + (lid & 15);
                int ch = ks * 2 + (lid >> 4);
                ldm_x4(a[ma], base + S_A + ar * 128 + ((ch ^ (ar & 7)) << 4));
            }
#pragma unroll
            for (int na = 0; na < 4; na++) {
                int nr = wn + na * 8 + (lid & 7);
                int ch = ks * 2 + ((lid >> 3) & 1);
                ldm_x2(b[na], base + S_W + nr * 128 + ((ch ^ (nr & 7)) << 4));
            }
#pragma unroll
            for (int ma = 0; ma < 4; ma++)
#pragma unroll
                for (int na = 0; na < 4; na++)
                    mma_f16(acc[ma][na], a[ma], b[na]);
        }
        __syncthreads();
    }

    const int g = lid >> 2;
    const int tg = (lid & 3) * 2;
    const int cstride = OUT_DIM * cs;
#pragma unroll
    for (int ma = 0; ma < 4; ma++) {
        int mr = bm + wm + ma * 16 + g;
#pragma unroll
        for (int na = 0; na < 4; na++) {
            int nc = bn + wn + na * 8 + tg;
            float b0 = bias[nc], b1 = bias[nc + 1];
            if (bias2) { b0 += bias2[nc]; b1 += bias2[nc + 1]; }
            float o00 = acc[ma][na][0] + b0, o01 = acc[ma][na][1] + b1;
            float o10 = acc[ma][na][2] + b0, o11 = acc[ma][na][3] + b1;
            if (Ch) {
                if (cs == 1) {
                    if (mr < M)
                        *(__half2*)(Ch + (size_t)mr * OUT_DIM + nc) = __floats2half2_rn(o00, o01);
                    if (mr + 8 < M)
                        *(__half2*)(Ch + (size_t)(mr + 8) * OUT_DIM + nc) = __floats2half2_rn(o10, o11);
                } else {
                    if (mr < M) {
                        Ch[(size_t)mr * cstride + 2 * nc + cp]       = __float2half_rn(o00);
                        Ch[(size_t)mr * cstride + 2 * (nc + 1) + cp] = __float2half_rn(o01);
                    }
                    if (mr + 8 < M) {
                        Ch[(size_t)(mr + 8) * cstride + 2 * nc + cp]       = __float2half_rn(o10);
                        Ch[(size_t)(mr + 8) * cstride + 2 * (nc + 1) + cp] = __float2half_rn(o11);
                    }
                }
            } else {
                if (mr < M)
                    *(float2*)(C + (size_t)mr * OUT_DIM + nc) = make_float2(o00, o01);
                if (mr + 8 < M)
                    *(float2*)(C + (size_t)(mr + 8) * OUT_DIM + nc) = make_float2(o10, o11);
            }
        }
    }
}

// ---------------- per-node attention: 64 thr/node, uint4 KV, 8-lane heads ----
// 4 nodes per 256-thr block. Warp covers 4 heads (8 lanes/head, 4 dims/lane).
// KV row = 64 uint4; lane's uint4 idx = head*8 + sub covers dims 4sub..4sub+3.
__global__ void __launch_bounds__(256)
attn_kernel(int N) {
    const int n = blockIdx.x * 4 + (threadIdx.x >> 6);
    if (n >= N) return;
    const int tid = threadIdx.x & 63;
    const int w = tid >> 5, lid = tid & 31;
    const int head = w * 4 + (lid >> 3);
    const int sub = lid & 7;
    const int qidx = head * 8 + sub;           // uint4 index in KV row / uint2 in Q row

    const int beg = g_ptr[n];
    const int end = g_ptr[n + 1];

    const uint2* Q2 = reinterpret_cast<const uint2*>(g_Qh);   // 64 uint2 per row
    const uint4* KV = reinterpret_cast<const uint4*>(g_KVh);  // 64 uint4 per row
    const int* __restrict__ src = g_src;

    uint2 qr = Q2[(size_t)n * 64 + qidx];
    float2 q01 = __half22float2(*(__half2*)&qr.x);   // dims 4sub, 4sub+1
    float2 q23 = __half22float2(*(__half2*)&qr.y);   // dims 4sub+2, 4sub+3
    const float inv_sqrt_dk = 0.17677669529663689f;

    float s = 0.f;
    float a0 = 0.f, a1 = 0.f, a2 = 0.f, a3 = 0.f;

    int i = beg;
    for (; i + 1 < end; i += 2) {
        int r0 = src[i], r1 = src[i + 1];
        uint4 kvA = KV[(size_t)r0 * 64 + qidx];
        uint4 kvB = KV[(size_t)r1 * 64 + qidx];
        // each half2 = (K_d, V_d)
        float2 A0 = __half22float2(*(__half2*)&kvA.x);
        float2 A1 = __half22float2(*(__half2*)&kvA.y);
        float2 A2 = __half22float2(*(__half2*)&kvA.z);
        float2 A3 = __half22float2(*(__half2*)&kvA.w);
        float2 B0 = __half22float2(*(__half2*)&kvB.x);
        float2 B1 = __half22float2(*(__half2*)&kvB.y);
        float2 B2 = __half22float2(*(__half2*)&kvB.z);
        float2 B3 = __half22float2(*(__half2*)&kvB.w);
        float pA = q01.x * A0.x + q01.y * A1.x + q23.x * A2.x + q23.y * A3.x;
        float pB = q01.x * B0.x + q01.y * B1.x + q23.x * B2.x + q23.y * B3.x;
        pA += __shfl_xor_sync(0xffffffffu, pA, 4);
        pB += __shfl_xor_sync(0xffffffffu, pB, 4);
        pA += __shfl_xor_sync(0xffffffffu, pA, 2);
        pB += __shfl_xor_sync(0xffffffffu, pB, 2);
        pA += __shfl_xor_sync(0xffffffffu, pA, 1);
        pB += __shfl_xor_sync(0xffffffffu, pB, 1);
        float eA = __expf(pA * inv_sqrt_dk);
        float eB = __expf(pB * inv_sqrt_dk);
        s += eA + eB;
        a0 += eA * A0.y + eB * B0.y;
        a1 += eA * A1.y + eB * B1.y;
        a2 += eA * A2.y + eB * B2.y;
        a3 += eA * A3.y + eB * B3.y;
    }
    if (i < end) {
        int r0 = src[i];
        uint4 kvA = KV[(size_t)r0 * 64 + qidx];
        float2 A0 = __half22float2(*(__half2*)&kvA.x);
        float2 A1 = __half22float2(*(__half2*)&kvA.y);
        float2 A2 = __half22float2(*(__half2*)&kvA.z);
        float2 A3 = __half22float2(*(__half2*)&kvA.w);
        float pA = q01.x * A0.x + q01.y * A1.x + q23.x * A2.x + q23.y * A3.x;
        pA += __shfl_xor_sync(0xffffffffu, pA, 4);
        pA += __shfl_xor_sync(0xffffffffu, pA, 2);
        pA += __shfl_xor_sync(0xffffffffu, pA, 1);
        float eA = __expf(pA * inv_sqrt_dk);
        s += eA;
        a0 += eA * A0.y;
        a1 += eA * A1.y;
        a2 += eA * A2.y;
        a3 += eA * A3.y;
    }

    float o0 = 0.f, o1 = 0.f, o2 = 0.f, o3 = 0.f;
    if (s > 0.f) {
        float inv = 1.f / s;
        o0 = a0 * inv; o1 = a1 * inv; o2 = a2 * inv; o3 = a3 * inv;
    }
    uint2 outv;
    *(__half2*)&outv.x = __floats2half2_rn(o0, o1);
    *(__half2*)&outv.y = __floats2half2_rn(o2, o3);
    reinterpret_cast<uint2*>(g_AG)[(size_t)n * 64 + qidx] = outv;
}

// ---------------- launch --------------------------------------------------------
extern "C" void kernel_launch(void* const* d_in, const int* in_sizes, int n_in,
                              void* d_out, int out_size) {
    const float* x    = (const float*)d_in[0];
    const int*   row  = (const int*)  d_in[1];
    const int*   col  = (const int*)  d_in[2];
    const float* rel  = (const float*)d_in[3];
    const float* user = (const float*)d_in[4];
    const float* item = (const float*)d_in[5];
    const float* Wq   = (const float*)d_in[6];
    const float* bq   = (const float*)d_in[7];
    const float* Wk   = (const float*)d_in[8];
    const float* bk   = (const float*)d_in[9];
    const float* Wv   = (const float*)d_in[10];
    const float* bv   = (const float*)d_in[11];
    const float* Wo   = (const float*)d_in[12];
    const float* bo   = (const float*)d_in[13];
    float* out = (float*)d_out;

    const int N  = in_sizes[0] / IN_DIM;
    const int E  = in_sizes[1];
    const int NU = in_sizes[4] / IN_DIM;
    const int E4 = E >> 2;

    __half *dQh, *dKVh, *dTE, *dX, *dAG, *dW;
    int* dDeg;
    cudaGetSymbolAddress((void**)&dQh,  g_Qh);
    cudaGetSymbolAddress((void**)&dKVh, g_KVh);
    cudaGetSymbolAddress((void**)&dTE,  g_TE);
    cudaGetSymbolAddress((void**)&dX,   g_X);
    cudaGetSymbolAddress((void**)&dAG,  g_AG);
    cudaGetSymbolAddress((void**)&dW,   g_W);
    cudaGetSymbolAddress((void**)&dDeg, g_deg);

    cudaFuncSetAttribute(gemm_f16_kernel,
                         cudaFuncAttributeMaxDynamicSharedMemorySize, GEMM_SMEM);

    // 1. fp16 conversions (2 launches)
    {
        int total4 = N * (IN_DIM / 4);
        int nu4 = NU * (IN_DIM / 4);
        cvt_ax_kernel<<<2048, 256>>>((const float4*)user, (const float4*)item,
                                     (const float4*)x, nu4, total4);
        cvt_w4_kernel<<<256, 256>>>((const float4*)Wq, (const float4*)Wk,
                                    (const float4*)Wv, (const float4*)Wo);
    }

    // 2. CSR build by destination (col)
    cudaMemsetAsync(dDeg, 0, (size_t)N * sizeof(int), 0);
    count_kernel<<<(E4 + 255) / 256, 256>>>((const int4*)col, E4, E, col);
    int nb = (N + 1023) / 1024;
    scan_partial_kernel<<<nb, 1024>>>(N);
    scan_add_kernel<<<(N + 255) / 256, 256>>>(N, E);
    scatter_kernel<<<(E4 + 255) / 256, 256>>>((const int4*)row, (const int4*)col,
                                              E4, E, row, col);

    // 3. projections (single-pass fp16 HMMA) -> fp16 intermediates
    dim3 gg((N + 127) / 128, 2);
    gemm_f16_kernel<<<gg, 256, GEMM_SMEM>>>(dTE, dW + 0 * 65536, bq, nullptr,
                                            nullptr, dQh, 1, 0, N);
    gemm_f16_kernel<<<gg, 256, GEMM_SMEM>>>(dTE, dW + 1 * 65536, bk, rel,
                                            nullptr, dKVh, 2, 0, N);
    gemm_f16_kernel<<<gg, 256, GEMM_SMEM>>>(dX,  dW + 2 * 65536, bv, nullptr,
                                            nullptr, dKVh, 2, 1, N);

    // 4. attention (64 thr/node, uint4 gathers)
    attn_kernel<<<(N + 3) / 4, 256>>>(N);

    // 5. output projection -> fp32 out
    gemm_f16_kernel<<<gg, 256, GEMM_SMEM>>>(dAG, dW + 3 * 65536, bo, nullptr,
                                            out, nullptr, 1, 0, N);
}

// round 13
// speedup vs baseline: 2.4948x; 1.1845x over previous
#include <cuda_runtime.h>
#include <cuda_bf16.h>
#include <cuda_fp16.h>
#include <math.h>
#include <stdint.h>

#define IN_DIM 256
#define OUT_DIM 256
#define DK 32
#define MAXN 50000
#define MAXE 800000

// ---------------- static device scratch (no cudaMalloc anywhere) ------------
__device__ __half g_TE [MAXN * IN_DIM];        // concat(user,item) fp16
__device__ __half g_X  [MAXN * IN_DIM];        // x fp16
__device__ __half g_AG [MAXN * OUT_DIM];       // attention output fp16
__device__ __half g_W  [4 * OUT_DIM * IN_DIM]; // Wq,Wk,Wv,Wo fp16
__device__ __half g_Qh [MAXN * OUT_DIM];
__device__ __half g_Kh [MAXN * OUT_DIM];       // K + rel, dense
__device__ __half g_Vh [MAXN * OUT_DIM];       // V, dense
__device__ int   g_deg[MAXN];
__device__ int   g_ptr[MAXN + 1];
__device__ int   g_cur[MAXN];
__device__ int   g_src[MAXE];
__device__ int   g_bsum[128];

// ---------------- asm helpers (family-common: sm_80+) -------------------------
__device__ __forceinline__ uint32_t smem_u32(const void* p) {
    uint32_t a;
    asm("{ .reg .u64 t; cvta.to.shared.u64 t, %1; cvt.u32.u64 %0, t; }"
        : "=r"(a) : "l"(p));
    return a;
}
__device__ __forceinline__ void cp16(uint32_t dst, const void* src, uint32_t bytes) {
    asm volatile("cp.async.cg.shared.global [%0], [%1], 16, %2;"
                 :: "r"(dst), "l"(src), "r"(bytes));
}
#define CP_COMMIT() asm volatile("cp.async.commit_group;" ::: "memory")
#define CP_WAIT(n)  asm volatile("cp.async.wait_group %0;" :: "n"(n) : "memory")

__device__ __forceinline__ void ldm_x4(uint32_t* r, uint32_t addr) {
    asm volatile("ldmatrix.sync.aligned.m8n8.x4.shared.b16 {%0,%1,%2,%3}, [%4];"
                 : "=r"(r[0]), "=r"(r[1]), "=r"(r[2]), "=r"(r[3]) : "r"(addr));
}
__device__ __forceinline__ void ldm_x2(uint32_t* r, uint32_t addr) {
    asm volatile("ldmatrix.sync.aligned.m8n8.x2.shared.b16 {%0,%1}, [%2];"
                 : "=r"(r[0]), "=r"(r[1]) : "r"(addr));
}
__device__ __forceinline__ void mma_f16(float* c, const uint32_t* a, const uint32_t* b) {
    asm volatile("mma.sync.aligned.m16n8k16.row.col.f32.f16.f16.f32 "
                 "{%0,%1,%2,%3}, {%4,%5,%6,%7}, {%8,%9}, {%0,%1,%2,%3};"
                 : "+f"(c[0]), "+f"(c[1]), "+f"(c[2]), "+f"(c[3])
                 : "r"(a[0]), "r"(a[1]), "r"(a[2]), "r"(a[3]), "r"(b[0]), "r"(b[1]));
}

// ---------------- merged prep: TE concat + x + all 4 W, fp32 -> fp16 ---------
__global__ void prep_kernel(const float4* __restrict__ user,
                            const float4* __restrict__ item,
                            const float4* __restrict__ x,
                            const float4* __restrict__ W0,
                            const float4* __restrict__ W1,
                            const float4* __restrict__ W2,
                            const float4* __restrict__ W3,
                            int nu4, int total4) {
    __half2* te = reinterpret_cast<__half2*>(g_TE);
    __half2* xx = reinterpret_cast<__half2*>(g_X);
    __half2* ww = reinterpret_cast<__half2*>(g_W);
    const float4* Ws[4] = {W0, W1, W2, W3};
    const int tot_ax = total4 * 2;          // TE + x items
    const int tot = tot_ax + 65536;         // + W items
    for (int i = blockIdx.x * blockDim.x + threadIdx.x; i < tot;
         i += gridDim.x * blockDim.x) {
        if (i < total4) {
            float4 v = (i < nu4) ? user[i] : item[i - nu4];
            te[2 * i]     = __floats2half2_rn(v.x, v.y);
            te[2 * i + 1] = __floats2half2_rn(v.z, v.w);
        } else if (i < tot_ax) {
            int j = i - total4;
            float4 v = x[j];
            xx[2 * j]     = __floats2half2_rn(v.x, v.y);
            xx[2 * j + 1] = __floats2half2_rn(v.z, v.w);
        } else {
            int j = i - tot_ax;
            float4 v = Ws[j >> 14][j & 16383];
            ww[2 * j]     = __floats2half2_rn(v.x, v.y);
            ww[2 * j + 1] = __floats2half2_rn(v.z, v.w);
        }
    }
}

// ---------------- CSR build ----------------------------------------------------
__global__ void count_kernel(const int4* __restrict__ col4, int E4, int E,
                             const int* __restrict__ col) {
    int i = blockIdx.x * blockDim.x + threadIdx.x;
    for (int e = i; e < E4; e += gridDim.x * blockDim.x) {
        int4 c = col4[e];
        atomicAdd(&g_deg[c.x], 1);
        atomicAdd(&g_deg[c.y], 1);
        atomicAdd(&g_deg[c.z], 1);
        atomicAdd(&g_deg[c.w], 1);
    }
    if (i == 0)
        for (int e = E4 * 4; e < E; e++) atomicAdd(&g_deg[col[e]], 1);
}
__global__ void scan_partial_kernel(int n) {
    __shared__ int sh[1024];
    int i = blockIdx.x * 1024 + threadIdx.x;
    int v = (i < n) ? g_deg[i] : 0;
    sh[threadIdx.x] = v;
    __syncthreads();
    for (int off = 1; off < 1024; off <<= 1) {
        int t = (threadIdx.x >= off) ? sh[threadIdx.x - off] : 0;
        __syncthreads();
        sh[threadIdx.x] += t;
        __syncthreads();
    }
    if (i < n) g_ptr[i] = sh[threadIdx.x] - v;
    if (threadIdx.x == 1023) g_bsum[blockIdx.x] = sh[1023];
}
__global__ void scan_add_kernel(int n, int E) {
    int i = blockIdx.x * blockDim.x + threadIdx.x;
    if (i < n) {
        int nb = i >> 10;
        int base = 0;
        for (int b = 0; b < nb; b++) base += g_bsum[b];
        int p = g_ptr[i] + base;
        g_ptr[i] = p;
        g_cur[i] = p;
    }
    if (i == 0) g_ptr[n] = E;
}
__global__ void scatter_kernel(const int4* __restrict__ row4,
                               const int4* __restrict__ col4, int E4, int E,
                               const int* __restrict__ row,
                               const int* __restrict__ col) {
    int i = blockIdx.x * blockDim.x + threadIdx.x;
    for (int e = i; e < E4; e += gridDim.x * blockDim.x) {
        int4 r = row4[e];
        int4 c = col4[e];
        g_src[atomicAdd(&g_cur[c.x], 1)] = r.x;
        g_src[atomicAdd(&g_cur[c.y], 1)] = r.y;
        g_src[atomicAdd(&g_cur[c.z], 1)] = r.z;
        g_src[atomicAdd(&g_cur[c.w], 1)] = r.w;
    }
    if (i == 0)
        for (int e = E4 * 4; e < E; e++)
            g_src[atomicAdd(&g_cur[col[e]], 1)] = row[e];
}

// ---------------- fp16 HMMA GEMM (single pass, K=256 in 4 k-tiles) ------------
// Dense coalesced outputs: fp16 Ch if non-null, else fp32 C.
#define S_A  0
#define S_W  16384
#define STG  32768
#define GEMM_SMEM (2 * STG)

__global__ void __launch_bounds__(256, 2)
gemm_f16_kernel(const __half* __restrict__ A, const __half* __restrict__ W,
                const float* __restrict__ bias, const float* __restrict__ bias2,
                float* __restrict__ C, __half* __restrict__ Ch, int M) {
    extern __shared__ char smem[];
    const uint32_t sb = smem_u32(smem);
    const int tid = threadIdx.x, wid = tid >> 5, lid = tid & 31;
    const int bm = blockIdx.x * 128;
    const int bn = blockIdx.y * 128;
    const int wm = (wid >> 2) * 64;
    const int wn = (wid & 3) * 32;

    float acc[4][4][4];
#pragma unroll
    for (int i = 0; i < 4; i++)
#pragma unroll
        for (int j = 0; j < 4; j++)
#pragma unroll
            for (int k = 0; k < 4; k++) acc[i][j][k] = 0.f;

    auto load_tile = [&](int kt, int stage) {
        const int koff = kt * 64;
        const uint32_t base = sb + stage * STG;
#pragma unroll
        for (int i = tid; i < 1024; i += 256) {
            int r = i >> 3, c = i & 7;
            int grow = bm + r;
            const char* g = (const char*)A + (size_t)grow * 512 + koff * 2 + c * 16;
            uint32_t d = base + S_A + r * 128 + ((c ^ (r & 7)) << 4);
            cp16(d, g, (grow < M) ? 16u : 0u);
        }
#pragma unroll
        for (int i = tid; i < 1024; i += 256) {
            int r = i >> 3, c = i & 7;
            const char* g = (const char*)W + (size_t)(bn + r) * 512 + koff * 2 + c * 16;
            uint32_t d = base + S_W + r * 128 + ((c ^ (r & 7)) << 4);
            cp16(d, g, 16u);
        }
        CP_COMMIT();
    };

    load_tile(0, 0);

#pragma unroll
    for (int t = 0; t < 4; t++) {
        const int st = t & 1;
        if (t + 1 < 4) {
            load_tile(t + 1, (t + 1) & 1);
            CP_WAIT(1);
        } else {
            CP_WAIT(0);
        }
        __syncthreads();

        const uint32_t base = sb + st * STG;
#pragma unroll
        for (int ks = 0; ks < 4; ks++) {
            uint32_t a[4][4], b[4][2];
#pragma unroll
            for (int ma = 0; ma < 4; ma++) {
                int ar = wm + ma * 16 + (lid & 15);
                int ch = ks * 2 + (lid >> 4);
                ldm_x4(a[ma], base + S_A + ar * 128 + ((ch ^ (ar & 7)) << 4));
            }
#pragma unroll
            for (int na = 0; na < 4; na++) {
                int nr = wn + na * 8 + (lid & 7);
                int ch = ks * 2 + ((lid >> 3) & 1);
                ldm_x2(b[na], base + S_W + nr * 128 + ((ch ^ (nr & 7)) << 4));
            }
#pragma unroll
            for (int ma = 0; ma < 4; ma++)
#pragma unroll
                for (int na = 0; na < 4; na++)
                    mma_f16(acc[ma][na], a[ma], b[na]);
        }
        __syncthreads();
    }

    const int g = lid >> 2;
    const int tg = (lid & 3) * 2;
#pragma unroll
    for (int ma = 0; ma < 4; ma++) {
        int mr = bm + wm + ma * 16 + g;
#pragma unroll
        for (int na = 0; na < 4; na++) {
            int nc = bn + wn + na * 8 + tg;
            float b0 = bias[nc], b1 = bias[nc + 1];
            if (bias2) { b0 += bias2[nc]; b1 += bias2[nc + 1]; }
            float o00 = acc[ma][na][0] + b0, o01 = acc[ma][na][1] + b1;
            float o10 = acc[ma][na][2] + b0, o11 = acc[ma][na][3] + b1;
            if (Ch) {
                if (mr < M)
                    *(__half2*)(Ch + (size_t)mr * OUT_DIM + nc) = __floats2half2_rn(o00, o01);
                if (mr + 8 < M)
                    *(__half2*)(Ch + (size_t)(mr + 8) * OUT_DIM + nc) = __floats2half2_rn(o10, o11);
            } else {
                if (mr < M)
                    *(float2*)(C + (size_t)mr * OUT_DIM + nc) = make_float2(o00, o01);
                if (mr + 8 < M)
                    *(float2*)(C + (size_t)(mr + 8) * OUT_DIM + nc) = make_float2(o10, o11);
            }
        }
    }
}

// ---------------- per-node attention: 64 thr/node, separate K/V, 4-edge ILP ---
// 4 nodes per 256-thr block. Warp covers 4 heads (8 lanes/head, 4 dims/lane).
__global__ void __launch_bounds__(256)
attn_kernel(int N) {
    const int n = blockIdx.x * 4 + (threadIdx.x >> 6);
    if (n >= N) return;
    const int tid = threadIdx.x & 63;
    const int w = tid >> 5, lid = tid & 31;
    const int head = w * 4 + (lid >> 3);
    const int sub = lid & 7;
    const int qidx = head * 8 + sub;     // uint2 index within a 64-uint2 row

    const int beg = g_ptr[n];
    const int end = g_ptr[n + 1];

    const uint2* Q2 = reinterpret_cast<const uint2*>(g_Qh);
    const uint2* K2 = reinterpret_cast<const uint2*>(g_Kh);
    const uint2* V2 = reinterpret_cast<const uint2*>(g_Vh);
    const int* __restrict__ src = g_src;

    uint2 qr = Q2[(size_t)n * 64 + qidx];
    float2 q01 = __half22float2(*(__half2*)&qr.x);
    float2 q23 = __half22float2(*(__half2*)&qr.y);
    const float inv_sqrt_dk = 0.17677669529663689f;

    float s = 0.f;
    float a0 = 0.f, a1 = 0.f, a2 = 0.f, a3 = 0.f;

    int i = beg;
    for (; i + 3 < end; i += 4) {
        int r0 = src[i], r1 = src[i + 1], r2 = src[i + 2], r3 = src[i + 3];
        uint2 k0 = K2[(size_t)r0 * 64 + qidx];
        uint2 k1 = K2[(size_t)r1 * 64 + qidx];
        uint2 k2 = K2[(size_t)r2 * 64 + qidx];
        uint2 k3 = K2[(size_t)r3 * 64 + qidx];
        uint2 v0 = V2[(size_t)r0 * 64 + qidx];
        uint2 v1 = V2[(size_t)r1 * 64 + qidx];
        uint2 v2 = V2[(size_t)r2 * 64 + qidx];
        uint2 v3 = V2[(size_t)r3 * 64 + qidx];

        float2 kA01 = __half22float2(*(__half2*)&k0.x), kA23 = __half22float2(*(__half2*)&k0.y);
        float2 kB01 = __half22float2(*(__half2*)&k1.x), kB23 = __half22float2(*(__half2*)&k1.y);
        float2 kC01 = __half22float2(*(__half2*)&k2.x), kC23 = __half22float2(*(__half2*)&k2.y);
        float2 kD01 = __half22float2(*(__half2*)&k3.x), kD23 = __half22float2(*(__half2*)&k3.y);

        float pA = q01.x * kA01.x + q01.y * kA01.y + q23.x * kA23.x + q23.y * kA23.y;
        float pB = q01.x * kB01.x + q01.y * kB01.y + q23.x * kB23.x + q23.y * kB23.y;
        float pC = q01.x * kC01.x + q01.y * kC01.y + q23.x * kC23.x + q23.y * kC23.y;
        float pD = q01.x * kD01.x + q01.y * kD01.y + q23.x * kD23.x + q23.y * kD23.y;

        pA += __shfl_xor_sync(0xffffffffu, pA, 4);
        pB += __shfl_xor_sync(0xffffffffu, pB, 4);
        pC += __shfl_xor_sync(0xffffffffu, pC, 4);
        pD += __shfl_xor_sync(0xffffffffu, pD, 4);
        pA += __shfl_xor_sync(0xffffffffu, pA, 2);
        pB += __shfl_xor_sync(0xffffffffu, pB, 2);
        pC += __shfl_xor_sync(0xffffffffu, pC, 2);
        pD += __shfl_xor_sync(0xffffffffu, pD, 2);
        pA += __shfl_xor_sync(0xffffffffu, pA, 1);
        pB += __shfl_xor_sync(0xffffffffu, pB, 1);
        pC += __shfl_xor_sync(0xffffffffu, pC, 1);
        pD += __shfl_xor_sync(0xffffffffu, pD, 1);

        float eA = __expf(pA * inv_sqrt_dk);
        float eB = __expf(pB * inv_sqrt_dk);
        float eC = __expf(pC * inv_sqrt_dk);
        float eD = __expf(pD * inv_sqrt_dk);
        s += (eA + eB) + (eC + eD);

        float2 vA01 = __half22float2(*(__half2*)&v0.x), vA23 = __half22float2(*(__half2*)&v0.y);
        float2 vB01 = __half22float2(*(__half2*)&v1.x), vB23 = __half22float2(*(__half2*)&v1.y);
        float2 vC01 = __half22float2(*(__half2*)&v2.x), vC23 = __half22float2(*(__half2*)&v2.y);
        float2 vD01 = __half22float2(*(__half2*)&v3.x), vD23 = __half22float2(*(__half2*)&v3.y);

        a0 += eA * vA01.x + eB * vB01.x + eC * vC01.x + eD * vD01.x;
        a1 += eA * vA01.y + eB * vB01.y + eC * vC01.y + eD * vD01.y;
        a2 += eA * vA23.x + eB * vB23.x + eC * vC23.x + eD * vD23.x;
        a3 += eA * vA23.y + eB * vB23.y + eC * vC23.y + eD * vD23.y;
    }
    for (; i < end; i++) {
        int r0 = src[i];
        uint2 k0 = K2[(size_t)r0 * 64 + qidx];
        uint2 v0 = V2[(size_t)r0 * 64 + qidx];
        float2 k01 = __half22float2(*(__half2*)&k0.x), k23 = __half22float2(*(__half2*)&k0.y);
        float p = q01.x * k01.x + q01.y * k01.y + q23.x * k23.x + q23.y * k23.y;
        p += __shfl_xor_sync(0xffffffffu, p, 4);
        p += __shfl_xor_sync(0xffffffffu, p, 2);
        p += __shfl_xor_sync(0xffffffffu, p, 1);
        float e = __expf(p * inv_sqrt_dk);
        s += e;
        float2 v01 = __half22float2(*(__half2*)&v0.x), v23 = __half22float2(*(__half2*)&v0.y);
        a0 += e * v01.x;
        a1 += e * v01.y;
        a2 += e * v23.x;
        a3 += e * v23.y;
    }

    float o0 = 0.f, o1 = 0.f, o2 = 0.f, o3 = 0.f;
    if (s > 0.f) {
        float inv = 1.f / s;
        o0 = a0 * inv; o1 = a1 * inv; o2 = a2 * inv; o3 = a3 * inv;
    }
    uint2 outv;
    *(__half2*)&outv.x = __floats2half2_rn(o0, o1);
    *(__half2*)&outv.y = __floats2half2_rn(o2, o3);
    reinterpret_cast<uint2*>(g_AG)[(size_t)n * 64 + qidx] = outv;
}

// ---------------- launch --------------------------------------------------------
extern "C" void kernel_launch(void* const* d_in, const int* in_sizes, int n_in,
                              void* d_out, int out_size) {
    const float* x    = (const float*)d_in[0];
    const int*   row  = (const int*)  d_in[1];
    const int*   col  = (const int*)  d_in[2];
    const float* rel  = (const float*)d_in[3];
    const float* user = (const float*)d_in[4];
    const float* item = (const float*)d_in[5];
    const float* Wq   = (const float*)d_in[6];
    const float* bq   = (const float*)d_in[7];
    const float* Wk   = (const float*)d_in[8];
    const float* bk   = (const float*)d_in[9];
    const float* Wv   = (const float*)d_in[10];
    const float* bv   = (const float*)d_in[11];
    const float* Wo   = (const float*)d_in[12];
    const float* bo   = (const float*)d_in[13];
    float* out = (float*)d_out;

    const int N  = in_sizes[0] / IN_DIM;
    const int E  = in_sizes[1];
    const int NU = in_sizes[4] / IN_DIM;
    const int E4 = E >> 2;

    __half *dQh, *dKh, *dVh, *dTE, *dX, *dAG, *dW;
    int* dDeg;
    cudaGetSymbolAddress((void**)&dQh,  g_Qh);
    cudaGetSymbolAddress((void**)&dKh,  g_Kh);
    cudaGetSymbolAddress((void**)&dVh,  g_Vh);
    cudaGetSymbolAddress((void**)&dTE,  g_TE);
    cudaGetSymbolAddress((void**)&dX,   g_X);
    cudaGetSymbolAddress((void**)&dAG,  g_AG);
    cudaGetSymbolAddress((void**)&dW,   g_W);
    cudaGetSymbolAddress((void**)&dDeg, g_deg);

    cudaFuncSetAttribute(gemm_f16_kernel,
                         cudaFuncAttributeMaxDynamicSharedMemorySize, GEMM_SMEM);

    // 1. merged fp16 prep (TE concat + x + all W) — one launch
    {
        int total4 = N * (IN_DIM / 4);
        int nu4 = NU * (IN_DIM / 4);
        prep_kernel<<<2304, 256>>>((const float4*)user, (const float4*)item,
                                   (const float4*)x,
                                   (const float4*)Wq, (const float4*)Wk,
                                   (const float4*)Wv, (const float4*)Wo,
                                   nu4, total4);
    }

    // 2. CSR build by destination (col)
    cudaMemsetAsync(dDeg, 0, (size_t)N * sizeof(int), 0);
    count_kernel<<<(E4 + 255) / 256, 256>>>((const int4*)col, E4, E, col);
    int nb = (N + 1023) / 1024;
    scan_partial_kernel<<<nb, 1024>>>(N);
    scan_add_kernel<<<(N + 255) / 256, 256>>>(N, E);
    scatter_kernel<<<(E4 + 255) / 256, 256>>>((const int4*)row, (const int4*)col,
                                              E4, E, row, col);

    // 3. projections (single-pass fp16 HMMA), dense coalesced outputs
    dim3 gg((N + 127) / 128, 2);
    gemm_f16_kernel<<<gg, 256, GEMM_SMEM>>>(dTE, dW + 0 * 65536, bq, nullptr,
                                            nullptr, dQh, N);
    gemm_f16_kernel<<<gg, 256, GEMM_SMEM>>>(dTE, dW + 1 * 65536, bk, rel,
                                            nullptr, dKh, N);
    gemm_f16_kernel<<<gg, 256, GEMM_SMEM>>>(dX,  dW + 2 * 65536, bv, nullptr,
                                            nullptr, dVh, N);

    // 4. attention (64 thr/node, 4-edge ILP, separate K/V gathers)
    attn_kernel<<<(N + 3) / 4, 256>>>(N);

    // 5. output projection -> fp32 out
    gemm_f16_kernel<<<gg, 256, GEMM_SMEM>>>(dAG, dW + 3 * 65536, bo, nullptr,
                                            out, nullptr, N);
}